// round 7
// baseline (speedup 1.0000x reference)
#include <cuda_runtime.h>
#include <cuda_fp16.h>
#include <math.h>
#include <stdint.h>

#define CC 32
#define HH 8
#define SS 128
#define II 256
#define JJ 256
#define NROW (SS*II)      // 32768 m-rows
#define ZROW (II*JJ)      // 65536 z-rows

#define LOG2E 1.44269504088896f

// Scratch (allocation-free): zero-init device globals.
__device__ __half g_qh[SS*HH*II*CC];  // [s][h][i][c], pre-scaled by 32^-0.5 * log2e
__device__ __half g_kh[SS*HH*II*CC];
__device__ __half g_vh[SS*HH*II*CC];
__device__ __half g_gh[SS*HH*II*CC];  // sigmoid(gate)
__device__ float  g_bf[HH*ZROW];      // [h][i][j] = b*log2e - 8*log2e
__device__ __half g_oh[NROW*HH*CC];   // [s][i][h*32+c], half2-packed

// ---------------------------------------------------------------------------
// helpers
// ---------------------------------------------------------------------------
__device__ __forceinline__ uint32_t packh2(float a, float b) {
    __half2 h = __floats2half2_rn(a, b);
    return *reinterpret_cast<uint32_t*>(&h);
}
__device__ __forceinline__ float2 h2f2(uint32_t u) {
    __half2 h = *reinterpret_cast<__half2*>(&u);
    return __half22float2(h);
}
__device__ __forceinline__ float ex2(float x) {
    float y;
    asm("ex2.approx.ftz.f32 %0, %1;" : "=f"(y) : "f"(x));
    return y;
}
__device__ __forceinline__ void mma_f16(
    float& d0, float& d1, float& d2, float& d3,
    uint32_t a0, uint32_t a1, uint32_t a2, uint32_t a3,
    uint32_t b0, uint32_t b1)
{
    asm volatile(
        "mma.sync.aligned.m16n8k16.row.col.f32.f16.f16.f32 "
        "{%0,%1,%2,%3},{%4,%5,%6,%7},{%8,%9},{%0,%1,%2,%3};"
        : "+f"(d0), "+f"(d1), "+f"(d2), "+f"(d3)
        : "r"(a0), "r"(a1), "r"(a2), "r"(a3), "r"(b0), "r"(b1));
}

// ---------------------------------------------------------------------------
// Kernel A: b[h][i][j] = (layernorm(z) @ wb)*log2e - 8*log2e, fp32, transposed.
// ---------------------------------------------------------------------------
__global__ __launch_bounds__(256) void bias_kernel(
    const float* __restrict__ z, const float* __restrict__ lnbs,
    const float* __restrict__ lnbb, const float* __restrict__ wb)
{
    __shared__ float swb[CC*HH];
    __shared__ float sls[CC];
    __shared__ float slb[CC];
    int t = threadIdx.x;
    if (t < CC*HH) swb[t] = wb[t];
    if (t < CC) { sls[t] = lnbs[t]; slb[t] = lnbb[t]; }
    __syncthreads();

    int row = blockIdx.x * 256 + t;          // row = i*256 + j
    const float4* zp = (const float4*)(z + (size_t)row * CC);
    float x[CC];
    #pragma unroll
    for (int q4 = 0; q4 < CC/4; q4++) {
        float4 f = zp[q4];
        x[4*q4+0]=f.x; x[4*q4+1]=f.y; x[4*q4+2]=f.z; x[4*q4+3]=f.w;
    }
    float mu = 0.f;
    #pragma unroll
    for (int c = 0; c < CC; c++) mu += x[c];
    mu *= (1.f/CC);
    float var = 0.f;
    #pragma unroll
    for (int c = 0; c < CC; c++) { float d = x[c]-mu; var += d*d; }
    var *= (1.f/CC);
    float rs = rsqrtf(var + 1e-5f);
    #pragma unroll
    for (int c = 0; c < CC; c++) x[c] = (x[c]-mu)*rs*sls[c] + slb[c];

    #pragma unroll
    for (int h = 0; h < HH; h++) {
        float acc = 0.f;
        #pragma unroll
        for (int c = 0; c < CC; c++) acc += x[c] * swb[c*HH + h];
        g_bf[h*ZROW + row] = acc * LOG2E - 8.0f * LOG2E;
    }
}

// ---------------------------------------------------------------------------
// Kernel B: layernorm(m) then q/k/v/gate projection via fp16 mma.
// ---------------------------------------------------------------------------
#define PROJ_SM_WORDS (8192 + 2048 + 128*33 + 64)
__global__ __launch_bounds__(256, 2) void proj_kernel(
    const float* __restrict__ m, const float* __restrict__ lns,
    const float* __restrict__ lnb,
    const float* __restrict__ wq, const float* __restrict__ wk,
    const float* __restrict__ wv, const float* __restrict__ wg)
{
    extern __shared__ uint32_t psm[];
    uint32_t* wS  = psm;                 // [512*16]
    uint32_t* mnS = wS + 8192;           // [128*16]
    float* msF = (float*)(mnS + 2048);   // [128][33]
    float* sls = msF + 128*33;
    float* slb = sls + 32;

    int t = threadIdx.x, lane = t & 31, w = t >> 5;
    int g = lane >> 2, tid = lane & 3;
    int mt = blockIdx.x >> 1, nh = blockIdx.x & 1;
    int r0 = mt * 128;
    const float sd = 0.176776695296636893f * LOG2E;   // folded exp2 scale

    for (int idx = t; idx < 8192; idx += 256) {
        int u = idx >> 9, n = idx & 511;
        int gcol = nh*512 + n;
        int tensor = gcol >> 8, nc = gcol & 255;
        const float* wp = (tensor==0) ? wq : (tensor==1) ? wk :
                          (tensor==2) ? wv : wg;
        float sc = (tensor==0) ? sd : 1.f;
        float w0 = wp[(2*u)*256 + nc] * sc;
        float w1 = wp[(2*u+1)*256 + nc] * sc;
        wS[n*16 + ((u + 2*n) & 15)] = packh2(w0, w1);
    }
    if (t < 32) { sls[t] = lns[t]; slb[t] = lnb[t]; }

    const float4* mp = (const float4*)(m + (size_t)r0 * CC);
    for (int idx = t; idx < 1024; idx += 256) {
        int r = idx >> 3, c4 = idx & 7;
        float4 f = mp[idx];
        msF[r*33 + 4*c4+0] = f.x; msF[r*33 + 4*c4+1] = f.y;
        msF[r*33 + 4*c4+2] = f.z; msF[r*33 + 4*c4+3] = f.w;
    }
    __syncthreads();

    if (t < 128) {
        float mu = 0.f;
        #pragma unroll
        for (int c = 0; c < CC; c++) mu += msF[t*33 + c];
        mu *= (1.f/CC);
        float var = 0.f;
        #pragma unroll
        for (int c = 0; c < CC; c++) { float d = msF[t*33+c]-mu; var += d*d; }
        var *= (1.f/CC);
        float rs = rsqrtf(var + 1e-5f);
        #pragma unroll
        for (int c = 0; c < CC; c++)
            msF[t*33 + c] = (msF[t*33+c]-mu)*rs*sls[c] + slb[c];
    }
    __syncthreads();

    for (int idx = t; idx < 2048; idx += 256) {
        int r = idx >> 4, u = idx & 15;
        mnS[r*16 + ((u + 2*r) & 15)] = packh2(msF[r*33 + 2*u], msF[r*33 + 2*u + 1]);
    }
    __syncthreads();

    int iw = w*16, ia = iw + g, ib = ia + 8;
    uint32_t A[2][4];
    #pragma unroll
    for (int kt = 0; kt < 2; kt++) {
        A[kt][0] = mnS[ia*16 + ((8*kt + tid     + 2*ia) & 15)];
        A[kt][1] = mnS[ib*16 + ((8*kt + tid     + 2*ib) & 15)];
        A[kt][2] = mnS[ia*16 + ((8*kt + tid + 4 + 2*ia) & 15)];
        A[kt][3] = mnS[ib*16 + ((8*kt + tid + 4 + 2*ib) & 15)];
    }
    int ra = r0 + ia, rb = r0 + ib;
    int sa = ra >> 8, ia2 = ra & 255;
    int sb = rb >> 8, ib2 = rb & 255;

    #pragma unroll
    for (int t2 = 0; t2 < 2; t2++) {
        int tensor = nh*2 + t2;
        __half* dsth = (tensor==0) ? g_qh : (tensor==1) ? g_kh :
                       (tensor==2) ? g_vh : g_gh;
        uint32_t* du = (uint32_t*)dsth;
        bool is_gate = (tensor == 3);
        #pragma unroll 4
        for (int nt2 = 0; nt2 < 32; nt2++) {
            int nt = t2*32 + nt2;
            int n = nt*8 + g;
            const uint32_t* wr = wS + n*16;
            int rot = 2*n;
            uint32_t b00 = wr[(tid      + rot) & 15];
            uint32_t b01 = wr[(tid + 4  + rot) & 15];
            uint32_t b10 = wr[(tid + 8  + rot) & 15];
            uint32_t b11 = wr[(tid + 12 + rot) & 15];
            float d0=0.f, d1=0.f, d2=0.f, d3=0.f;
            mma_f16(d0,d1,d2,d3, A[0][0],A[0][1],A[0][2],A[0][3], b00,b01);
            mma_f16(d0,d1,d2,d3, A[1][0],A[1][1],A[1][2],A[1][3], b10,b11);
            if (is_gate) {
                d0 = 1.f/(1.f + __expf(-d0));
                d1 = 1.f/(1.f + __expf(-d1));
                d2 = 1.f/(1.f + __expf(-d2));
                d3 = 1.f/(1.f + __expf(-d3));
            }
            int nc8 = (nt*8 + 2*tid) & 255;      // col within tensor
            int h = nc8 >> 5, cu = (nc8 & 31) >> 1;
            du[(size_t)((sa*HH + h)*II + ia2)*16 + cu] = packh2(d0, d1);
            du[(size_t)((sb*HH + h)*II + ib2)*16 + cu] = packh2(d2, d3);
        }
    }
}

// ---------------------------------------------------------------------------
// Kernel C: attention per (s,h); fp16 mma; exp2-domain scores; bias for chunk
//   ch+1 prefetched into regs during chunk ch; chunk loop unrolled so AV(ch)
//   can overlap QK(ch+1).
// ---------------------------------------------------------------------------
__global__ __launch_bounds__(256, 2) void attn_kernel()
{
    __shared__ uint32_t Ksb[256*16];    // 16 KB
    __shared__ uint32_t Vtb[32*128];    // 16 KB

    int t = threadIdx.x, lane = t & 31, w = t >> 5;
    int g = lane >> 2, tid = lane & 3;
    int h = blockIdx.x & 7, s = blockIdx.x >> 3;
    size_t blk = (size_t)(s*HH + h) * (II*CC/2);   // half2-unit base
    const uint32_t* khu = (const uint32_t*)g_kh + blk;
    const uint16_t* vhu = (const uint16_t*)g_vh + blk*2;
    const uint32_t* qhu = (const uint32_t*)g_qh + blk;
    const uint32_t* ghu = (const uint32_t*)g_gh + blk;
    const float* bfp = g_bf + (size_t)h*ZROW;

    for (int idx = t; idx < 4096; idx += 256) {
        int j = idx >> 4, u = idx & 15;
        Ksb[j*16 + ((u + 2*j) & 15)] = khu[idx];
    }
    for (int idx = t; idx < 4096; idx += 256) {
        int u = idx >> 5, c = idx & 31;
        uint32_t lo = vhu[(2*u)*32 + c];
        uint32_t hi = vhu[(2*u+1)*32 + c];
        Vtb[c*128 + ((u + 4*c) & 127)] = lo | (hi << 16);
    }
    __syncthreads();

    #pragma unroll 1
    for (int round = 0; round < 2; round++) {
        int iw = round*128 + w*16;
        int ia = iw + g, ib = ia + 8;

        uint32_t A[2][4];
        #pragma unroll
        for (int kt = 0; kt < 2; kt++) {
            A[kt][0] = qhu[ia*16 + 8*kt + tid];
            A[kt][1] = qhu[ib*16 + 8*kt + tid];
            A[kt][2] = qhu[ia*16 + 8*kt + tid + 4];
            A[kt][3] = qhu[ib*16 + 8*kt + tid + 4];
        }
        const float2* b0f = (const float2*)(bfp + (size_t)ia*JJ);
        const float2* b1f = (const float2*)(bfp + (size_t)ib*JJ);

        float s0a = 0.f, s0b = 0.f, s1a = 0.f, s1b = 0.f;
        float D0[4], D1[4], D2[4], D3[4];
        #pragma unroll
        for (int k = 0; k < 4; k++) { D0[k]=0.f; D1[k]=0.f; D2[k]=0.f; D3[k]=0.f; }

        // prefetch chunk 0 bias
        float2 C0[8], C1[8];
        #pragma unroll
        for (int nt = 0; nt < 8; nt++) {
            C0[nt] = b0f[nt*4 + tid];
            C1[nt] = b1f[nt*4 + tid];
        }

        #pragma unroll
        for (int ch = 0; ch < 4; ch++) {
            int u0 = (ch+1)*32;        // next chunk's float2 unit offset
            float S0[16], S1[16];
            #pragma unroll
            for (int nt = 0; nt < 8; nt++) {
                S0[2*nt] = C0[nt].x; S0[2*nt+1] = C0[nt].y;
                S1[2*nt] = C1[nt].x; S1[2*nt+1] = C1[nt].y;
            }
            // prefetch next chunk's bias while QK mma runs
            if (ch < 3) {
                #pragma unroll
                for (int nt = 0; nt < 8; nt++) {
                    C0[nt] = b0f[u0 + nt*4 + tid];
                    C1[nt] = b1f[u0 + nt*4 + tid];
                }
            }
            // QK^T
            #pragma unroll
            for (int nt = 0; nt < 8; nt++) {
                int j = ch*64 + nt*8 + g;
                const uint32_t* kr = Ksb + j*16;
                int rot = 2*j;
                uint32_t b00 = kr[(tid      + rot) & 15];
                uint32_t b01 = kr[(tid + 4  + rot) & 15];
                uint32_t b10 = kr[(tid + 8  + rot) & 15];
                uint32_t b11 = kr[(tid + 12 + rot) & 15];
                mma_f16(S0[2*nt], S0[2*nt+1], S1[2*nt], S1[2*nt+1],
                        A[0][0], A[0][1], A[0][2], A[0][3], b00, b01);
                mma_f16(S0[2*nt], S0[2*nt+1], S1[2*nt], S1[2*nt+1],
                        A[1][0], A[1][1], A[1][2], A[1][3], b10, b11);
            }
            // single-op exp2; pack for AV
            uint32_t h0[8], h1[8];
            #pragma unroll
            for (int nt = 0; nt < 8; nt++) {
                float e0 = ex2(S0[2*nt]);
                float e1 = ex2(S0[2*nt+1]);
                float e2 = ex2(S1[2*nt]);
                float e3 = ex2(S1[2*nt+1]);
                if (nt & 1) { s0b += e0 + e1; s1b += e2 + e3; }
                else        { s0a += e0 + e1; s1a += e2 + e3; }
                h0[nt] = packh2(e0, e1);
                h1[nt] = packh2(e2, e3);
            }
            #pragma unroll
            for (int kt = 0; kt < 4; kt++) {
                uint32_t a0 = h0[2*kt], a1 = h1[2*kt];
                uint32_t a2 = h0[2*kt+1], a3 = h1[2*kt+1];
                int ktg = ch*4 + kt;
                #pragma unroll
                for (int nv = 0; nv < 4; nv++) {
                    int c = nv*8 + g;
                    const uint32_t* vr = Vtb + c*128;
                    int rot = 4*c + 8*ktg + tid;
                    uint32_t b0 = vr[ rot      & 127];
                    uint32_t b1 = vr[(rot + 4) & 127];
                    float* D = (nv==0) ? D0 : (nv==1) ? D1 : (nv==2) ? D2 : D3;
                    mma_f16(D[0], D[1], D[2], D[3], a0, a1, a2, a3, b0, b1);
                }
            }
        }

        float s0 = s0a + s0b, s1 = s1a + s1b;
        s0 += __shfl_xor_sync(0xffffffffu, s0, 1);
        s0 += __shfl_xor_sync(0xffffffffu, s0, 2);
        s1 += __shfl_xor_sync(0xffffffffu, s1, 1);
        s1 += __shfl_xor_sync(0xffffffffu, s1, 2);
        float inv0 = 1.f / s0, inv1 = 1.f / s1;

        // epilogue: gate + store half2
        uint32_t* ou = (uint32_t*)g_oh;
        #pragma unroll
        for (int nv = 0; nv < 4; nv++) {
            const float* D = (nv==0) ? D0 : (nv==1) ? D1 : (nv==2) ? D2 : D3;
            float2 ga = h2f2(ghu[ia*16 + nv*4 + tid]);
            float2 gb = h2f2(ghu[ib*16 + nv*4 + tid]);
            int cu = (h*CC)/2 + nv*4 + tid;
            ou[(size_t)(s*II + ia)*(HH*CC/2) + cu] = packh2(D[0]*inv0*ga.x, D[1]*inv0*ga.y);
            ou[(size_t)(s*II + ib)*(HH*CC/2) + cu] = packh2(D[2]*inv1*gb.x, D[3]*inv1*gb.y);
        }
    }
}

// ---------------------------------------------------------------------------
// Kernel D: out = o @ wo + bo via fp16 m16n8k16. M-tile=64, 128 threads.
//   o tile batched into registers FIRST; wT staging work hides the latency.
// ---------------------------------------------------------------------------
#define OUT_SMEM_BYTES ((64*132 + 32*128 + 32) * 4)
__global__ __launch_bounds__(128, 4) void outproj_kernel(
    const float* __restrict__ wo, const float* __restrict__ bo,
    float* __restrict__ out)
{
    extern __shared__ uint32_t smu[];
    uint32_t* oS = smu;                 // [64][132]
    uint32_t* wT = oS + 64*132;         // [32][128]
    float*   sbo = (float*)(wT + 32*128);

    int t = threadIdx.x, lane = t & 31, w = t >> 5;
    int g = lane >> 2, tid = lane & 3;
    int r0 = blockIdx.x * 64;

    // 1) issue all o loads (16 uint4 per thread, coalesced) -- they fly
    //    while the wT staging below executes.
    uint4 ov[16];
    const uint4* op = (const uint4*)((const uint32_t*)g_oh + (size_t)r0*(HH*CC/2));
    #pragma unroll
    for (int i = 0; i < 16; i++) ov[i] = op[t + 128*i];

    // 2) independent work: stage wo transposed + cvt
    for (int idx = t; idx < 4096; idx += 128) {
        int u = idx >> 5, c = idx & 31;
        float w0 = wo[(2*u)*32 + c];
        float w1 = wo[(2*u+1)*32 + c];
        wT[c*128 + ((u + 4*c) & 127)] = packh2(w0, w1);
    }
    if (t < 32) sbo[t] = bo[t];

    // 3) store o tiles to smem
    #pragma unroll
    for (int i = 0; i < 16; i++) {
        int idx = t + 128*i;
        int r = idx >> 5, u4 = idx & 31;
        *(uint4*)&oS[r*132 + 4*u4] = ov[i];
    }
    __syncthreads();

    int iw = w*16;
    float D0[4], D1[4], D2[4], D3[4];
    #pragma unroll
    for (int k = 0; k < 4; k++) { D0[k]=0.f; D1[k]=0.f; D2[k]=0.f; D3[k]=0.f; }

    #pragma unroll 4
    for (int kt = 0; kt < 16; kt++) {
        int u = 8*kt + tid;
        uint32_t a0 = oS[(iw+g  )*132 + u];
        uint32_t a1 = oS[(iw+g+8)*132 + u];
        uint32_t a2 = oS[(iw+g  )*132 + u + 4];
        uint32_t a3 = oS[(iw+g+8)*132 + u + 4];
        #pragma unroll
        for (int nt = 0; nt < 4; nt++) {
            int c = nt*8 + g;
            const uint32_t* wr = wT + c*128;
            int rot = 4*c + 8*kt + tid;
            uint32_t b0 = wr[ rot      & 127];
            uint32_t b1 = wr[(rot + 4) & 127];
            float* D = (nt == 0) ? D0 : (nt == 1) ? D1 : (nt == 2) ? D2 : D3;
            mma_f16(D[0], D[1], D[2], D[3], a0, a1, a2, a3, b0, b1);
        }
    }

    int ra = r0 + iw + g, rb = r0 + iw + g + 8;
    #pragma unroll
    for (int nt = 0; nt < 4; nt++) {
        const float* D = (nt == 0) ? D0 : (nt == 1) ? D1 : (nt == 2) ? D2 : D3;
        int c = nt*8 + 2*tid;
        float2 bb = make_float2(sbo[c], sbo[c+1]);
        *(float2*)&out[(size_t)ra*CC + c] = make_float2(D[0] + bb.x, D[1] + bb.y);
        *(float2*)&out[(size_t)rb*CC + c] = make_float2(D[2] + bb.x, D[3] + bb.y);
    }
}

// ---------------------------------------------------------------------------
extern "C" void kernel_launch(void* const* d_in, const int* in_sizes, int n_in,
                              void* d_out, int out_size)
{
    const float* m         = (const float*)d_in[0];
    const float* z         = (const float*)d_in[1];
    const float* ln_scale  = (const float*)d_in[2];
    const float* ln_bias   = (const float*)d_in[3];
    const float* lnb_scale = (const float*)d_in[4];
    const float* lnb_bias  = (const float*)d_in[5];
    const float* wq        = (const float*)d_in[6];
    const float* wk        = (const float*)d_in[7];
    const float* wv        = (const float*)d_in[8];
    const float* wb        = (const float*)d_in[9];
    const float* wg        = (const float*)d_in[10];
    const float* wo        = (const float*)d_in[11];
    const float* bo        = (const float*)d_in[12];
    float* out = (float*)d_out;

    cudaFuncSetAttribute(proj_kernel, cudaFuncAttributeMaxDynamicSharedMemorySize,
                         PROJ_SM_WORDS * 4);
    cudaFuncSetAttribute(outproj_kernel, cudaFuncAttributeMaxDynamicSharedMemorySize,
                         OUT_SMEM_BYTES);

    bias_kernel<<<ZROW/256, 256>>>(z, lnb_scale, lnb_bias, wb);
    proj_kernel<<<(NROW/128)*2, 256, PROJ_SM_WORDS*4>>>(m, ln_scale, ln_bias, wq, wk, wv, wg);
    attn_kernel<<<SS*HH, 256>>>();
    outproj_kernel<<<NROW/64, 128, OUT_SMEM_BYTES>>>(wo, bo, out);
}

// round 9
// speedup vs baseline: 1.0340x; 1.0340x over previous
#include <cuda_runtime.h>
#include <cuda_fp16.h>
#include <math.h>
#include <stdint.h>

#define CC 32
#define HH 8
#define SS 128
#define II 256
#define JJ 256
#define NROW (SS*II)      // 32768 m-rows
#define ZROW (II*JJ)      // 65536 z-rows

#define LOG2E 1.44269504088896f

// Scratch (allocation-free): zero-init device globals.
__device__ __half g_qh[SS*HH*II*CC];  // [s][h][i][c], pre-scaled by 32^-0.5 * log2e
__device__ __half g_kh[SS*HH*II*CC];
__device__ __half g_vh[SS*HH*II*CC];
__device__ __half g_gh[SS*HH*II*CC];  // sigmoid(gate)
__device__ float  g_bf[HH*ZROW];      // [h][i][j] = b*log2e - 8*log2e
__device__ __half g_oh[NROW*HH*CC];   // [s][i][h*32+c], half2-packed

// ---------------------------------------------------------------------------
// helpers
// ---------------------------------------------------------------------------
__device__ __forceinline__ uint32_t packh2(float a, float b) {
    __half2 h = __floats2half2_rn(a, b);
    return *reinterpret_cast<uint32_t*>(&h);
}
__device__ __forceinline__ float2 h2f2(uint32_t u) {
    __half2 h = *reinterpret_cast<__half2*>(&u);
    return __half22float2(h);
}
__device__ __forceinline__ float ex2(float x) {
    float y;
    asm("ex2.approx.ftz.f32 %0, %1;" : "=f"(y) : "f"(x));
    return y;
}
__device__ __forceinline__ void mma_f16(
    float& d0, float& d1, float& d2, float& d3,
    uint32_t a0, uint32_t a1, uint32_t a2, uint32_t a3,
    uint32_t b0, uint32_t b1)
{
    asm volatile(
        "mma.sync.aligned.m16n8k16.row.col.f32.f16.f16.f32 "
        "{%0,%1,%2,%3},{%4,%5,%6,%7},{%8,%9},{%0,%1,%2,%3};"
        : "+f"(d0), "+f"(d1), "+f"(d2), "+f"(d3)
        : "r"(a0), "r"(a1), "r"(a2), "r"(a3), "r"(b0), "r"(b1));
}

// ---------------------------------------------------------------------------
// Kernel A: b[h][i][j] = (layernorm(z) @ wb)*log2e - 8*log2e, fp32, transposed.
// ---------------------------------------------------------------------------
__global__ __launch_bounds__(256) void bias_kernel(
    const float* __restrict__ z, const float* __restrict__ lnbs,
    const float* __restrict__ lnbb, const float* __restrict__ wb)
{
    __shared__ float swb[CC*HH];
    __shared__ float sls[CC];
    __shared__ float slb[CC];
    int t = threadIdx.x;
    if (t < CC*HH) swb[t] = wb[t];
    if (t < CC) { sls[t] = lnbs[t]; slb[t] = lnbb[t]; }
    __syncthreads();

    int row = blockIdx.x * 256 + t;          // row = i*256 + j
    const float4* zp = (const float4*)(z + (size_t)row * CC);
    float x[CC];
    #pragma unroll
    for (int q4 = 0; q4 < CC/4; q4++) {
        float4 f = zp[q4];
        x[4*q4+0]=f.x; x[4*q4+1]=f.y; x[4*q4+2]=f.z; x[4*q4+3]=f.w;
    }
    float mu = 0.f;
    #pragma unroll
    for (int c = 0; c < CC; c++) mu += x[c];
    mu *= (1.f/CC);
    float var = 0.f;
    #pragma unroll
    for (int c = 0; c < CC; c++) { float d = x[c]-mu; var += d*d; }
    var *= (1.f/CC);
    float rs = rsqrtf(var + 1e-5f);
    #pragma unroll
    for (int c = 0; c < CC; c++) x[c] = (x[c]-mu)*rs*sls[c] + slb[c];

    #pragma unroll
    for (int h = 0; h < HH; h++) {
        float acc = 0.f;
        #pragma unroll
        for (int c = 0; c < CC; c++) acc += x[c] * swb[c*HH + h];
        g_bf[h*ZROW + row] = acc * LOG2E - 8.0f * LOG2E;
    }
}

// ---------------------------------------------------------------------------
// Kernel B: layernorm(m) then q/k/v/gate projection via fp16 mma.
// ---------------------------------------------------------------------------
#define PROJ_SM_WORDS (8192 + 2048 + 128*33 + 64)
__global__ __launch_bounds__(256, 3) void proj_kernel(
    const float* __restrict__ m, const float* __restrict__ lns,
    const float* __restrict__ lnb,
    const float* __restrict__ wq, const float* __restrict__ wk,
    const float* __restrict__ wv, const float* __restrict__ wg)
{
    extern __shared__ uint32_t psm[];
    uint32_t* wS  = psm;                 // [512*16]
    uint32_t* mnS = wS + 8192;           // [128*16]
    float* msF = (float*)(mnS + 2048);   // [128][33]
    float* sls = msF + 128*33;
    float* slb = sls + 32;

    int t = threadIdx.x, lane = t & 31, w = t >> 5;
    int g = lane >> 2, tid = lane & 3;
    int mt = blockIdx.x >> 1, nh = blockIdx.x & 1;
    int r0 = mt * 128;
    const float sd = 0.176776695296636893f * LOG2E;   // folded exp2 scale

    for (int idx = t; idx < 8192; idx += 256) {
        int u = idx >> 9, n = idx & 511;
        int gcol = nh*512 + n;
        int tensor = gcol >> 8, nc = gcol & 255;
        const float* wp = (tensor==0) ? wq : (tensor==1) ? wk :
                          (tensor==2) ? wv : wg;
        float sc = (tensor==0) ? sd : 1.f;
        float w0 = wp[(2*u)*256 + nc] * sc;
        float w1 = wp[(2*u+1)*256 + nc] * sc;
        wS[n*16 + ((u + 2*n) & 15)] = packh2(w0, w1);
    }
    if (t < 32) { sls[t] = lns[t]; slb[t] = lnb[t]; }

    const float4* mp = (const float4*)(m + (size_t)r0 * CC);
    for (int idx = t; idx < 1024; idx += 256) {
        int r = idx >> 3, c4 = idx & 7;
        float4 f = mp[idx];
        msF[r*33 + 4*c4+0] = f.x; msF[r*33 + 4*c4+1] = f.y;
        msF[r*33 + 4*c4+2] = f.z; msF[r*33 + 4*c4+3] = f.w;
    }
    __syncthreads();

    if (t < 128) {
        float mu = 0.f;
        #pragma unroll
        for (int c = 0; c < CC; c++) mu += msF[t*33 + c];
        mu *= (1.f/CC);
        float var = 0.f;
        #pragma unroll
        for (int c = 0; c < CC; c++) { float d = msF[t*33+c]-mu; var += d*d; }
        var *= (1.f/CC);
        float rs = rsqrtf(var + 1e-5f);
        #pragma unroll
        for (int c = 0; c < CC; c++)
            msF[t*33 + c] = (msF[t*33+c]-mu)*rs*sls[c] + slb[c];
    }
    __syncthreads();

    for (int idx = t; idx < 2048; idx += 256) {
        int r = idx >> 4, u = idx & 15;
        mnS[r*16 + ((u + 2*r) & 15)] = packh2(msF[r*33 + 2*u], msF[r*33 + 2*u + 1]);
    }
    __syncthreads();

    int iw = w*16, ia = iw + g, ib = ia + 8;
    uint32_t A[2][4];
    #pragma unroll
    for (int kt = 0; kt < 2; kt++) {
        A[kt][0] = mnS[ia*16 + ((8*kt + tid     + 2*ia) & 15)];
        A[kt][1] = mnS[ib*16 + ((8*kt + tid     + 2*ib) & 15)];
        A[kt][2] = mnS[ia*16 + ((8*kt + tid + 4 + 2*ia) & 15)];
        A[kt][3] = mnS[ib*16 + ((8*kt + tid + 4 + 2*ib) & 15)];
    }
    int ra = r0 + ia, rb = r0 + ib;
    int sa = ra >> 8, ia2 = ra & 255;
    int sb = rb >> 8, ib2 = rb & 255;

    #pragma unroll
    for (int t2 = 0; t2 < 2; t2++) {
        int tensor = nh*2 + t2;
        __half* dsth = (tensor==0) ? g_qh : (tensor==1) ? g_kh :
                       (tensor==2) ? g_vh : g_gh;
        uint32_t* du = (uint32_t*)dsth;
        bool is_gate = (tensor == 3);
        #pragma unroll 4
        for (int nt2 = 0; nt2 < 32; nt2++) {
            int nt = t2*32 + nt2;
            int n = nt*8 + g;
            const uint32_t* wr = wS + n*16;
            int rot = 2*n;
            uint32_t b00 = wr[(tid      + rot) & 15];
            uint32_t b01 = wr[(tid + 4  + rot) & 15];
            uint32_t b10 = wr[(tid + 8  + rot) & 15];
            uint32_t b11 = wr[(tid + 12 + rot) & 15];
            float d0=0.f, d1=0.f, d2=0.f, d3=0.f;
            mma_f16(d0,d1,d2,d3, A[0][0],A[0][1],A[0][2],A[0][3], b00,b01);
            mma_f16(d0,d1,d2,d3, A[1][0],A[1][1],A[1][2],A[1][3], b10,b11);
            if (is_gate) {
                d0 = 1.f/(1.f + __expf(-d0));
                d1 = 1.f/(1.f + __expf(-d1));
                d2 = 1.f/(1.f + __expf(-d2));
                d3 = 1.f/(1.f + __expf(-d3));
            }
            int nc8 = (nt*8 + 2*tid) & 255;      // col within tensor
            int h = nc8 >> 5, cu = (nc8 & 31) >> 1;
            du[(size_t)((sa*HH + h)*II + ia2)*16 + cu] = packh2(d0, d1);
            du[(size_t)((sb*HH + h)*II + ib2)*16 + cu] = packh2(d2, d3);
        }
    }
}

// ---------------------------------------------------------------------------
// Kernel C: attention per (s,h); fp16 mma; exp2-domain scores (q pre-scaled by
//   sd*log2e, bias by log2e with -8*log2e folded). 3 CTAs/SM for latency hiding.
// ---------------------------------------------------------------------------
__global__ __launch_bounds__(256, 3) void attn_kernel()
{
    __shared__ uint32_t Ksb[256*16];    // 16 KB
    __shared__ uint32_t Vtb[32*128];    // 16 KB

    int t = threadIdx.x, lane = t & 31, w = t >> 5;
    int g = lane >> 2, tid = lane & 3;
    int h = blockIdx.x & 7, s = blockIdx.x >> 3;
    size_t blk = (size_t)(s*HH + h) * (II*CC/2);   // half2-unit base
    const uint32_t* khu = (const uint32_t*)g_kh + blk;
    const uint16_t* vhu = (const uint16_t*)g_vh + blk*2;
    const uint32_t* qhu = (const uint32_t*)g_qh + blk;
    const uint32_t* ghu = (const uint32_t*)g_gh + blk;
    const float* bfp = g_bf + (size_t)h*ZROW;

    for (int idx = t; idx < 4096; idx += 256) {
        int j = idx >> 4, u = idx & 15;
        Ksb[j*16 + ((u + 2*j) & 15)] = khu[idx];
    }
    for (int idx = t; idx < 4096; idx += 256) {
        int u = idx >> 5, c = idx & 31;
        uint32_t lo = vhu[(2*u)*32 + c];
        uint32_t hi = vhu[(2*u+1)*32 + c];
        Vtb[c*128 + ((u + 4*c) & 127)] = lo | (hi << 16);
    }
    __syncthreads();

    #pragma unroll 1
    for (int round = 0; round < 2; round++) {
        int iw = round*128 + w*16;
        int ia = iw + g, ib = ia + 8;

        uint32_t A[2][4];
        #pragma unroll
        for (int kt = 0; kt < 2; kt++) {
            A[kt][0] = qhu[ia*16 + 8*kt + tid];
            A[kt][1] = qhu[ib*16 + 8*kt + tid];
            A[kt][2] = qhu[ia*16 + 8*kt + tid + 4];
            A[kt][3] = qhu[ib*16 + 8*kt + tid + 4];
        }
        const float2* b0f = (const float2*)(bfp + (size_t)ia*JJ);
        const float2* b1f = (const float2*)(bfp + (size_t)ib*JJ);

        float s0a = 0.f, s0b = 0.f, s1a = 0.f, s1b = 0.f;
        float D0[4], D1[4], D2[4], D3[4];
        #pragma unroll
        for (int k = 0; k < 4; k++) { D0[k]=0.f; D1[k]=0.f; D2[k]=0.f; D3[k]=0.f; }

        #pragma unroll 1
        for (int ch = 0; ch < 4; ch++) {
            int u0 = ch*32;            // float2 unit offset (64 j)
            float S0[16], S1[16];
            // bias (exp2-domain, shift folded) as initial accumulator
            #pragma unroll
            for (int nt = 0; nt < 8; nt++) {
                float2 bf = b0f[u0 + nt*4 + tid];
                S0[2*nt] = bf.x; S0[2*nt+1] = bf.y;
                bf = b1f[u0 + nt*4 + tid];
                S1[2*nt] = bf.x; S1[2*nt+1] = bf.y;
            }
            // QK^T
            #pragma unroll
            for (int nt = 0; nt < 8; nt++) {
                int j = ch*64 + nt*8 + g;
                const uint32_t* kr = Ksb + j*16;
                int rot = 2*j;
                uint32_t b00 = kr[(tid      + rot) & 15];
                uint32_t b01 = kr[(tid + 4  + rot) & 15];
                uint32_t b10 = kr[(tid + 8  + rot) & 15];
                uint32_t b11 = kr[(tid + 12 + rot) & 15];
                mma_f16(S0[2*nt], S0[2*nt+1], S1[2*nt], S1[2*nt+1],
                        A[0][0], A[0][1], A[0][2], A[0][3], b00, b01);
                mma_f16(S0[2*nt], S0[2*nt+1], S1[2*nt], S1[2*nt+1],
                        A[1][0], A[1][1], A[1][2], A[1][3], b10, b11);
            }
            // single-op exp2; pack for AV
            uint32_t h0[8], h1[8];
            #pragma unroll
            for (int nt = 0; nt < 8; nt++) {
                float e0 = ex2(S0[2*nt]);
                float e1 = ex2(S0[2*nt+1]);
                float e2 = ex2(S1[2*nt]);
                float e3 = ex2(S1[2*nt+1]);
                if (nt & 1) { s0b += e0 + e1; s1b += e2 + e3; }
                else        { s0a += e0 + e1; s1a += e2 + e3; }
                h0[nt] = packh2(e0, e1);
                h1[nt] = packh2(e2, e3);
            }
            #pragma unroll
            for (int kt = 0; kt < 4; kt++) {
                uint32_t a0 = h0[2*kt], a1 = h1[2*kt];
                uint32_t a2 = h0[2*kt+1], a3 = h1[2*kt+1];
                int ktg = ch*4 + kt;
                #pragma unroll
                for (int nv = 0; nv < 4; nv++) {
                    int c = nv*8 + g;
                    const uint32_t* vr = Vtb + c*128;
                    int rot = 4*c + 8*ktg + tid;
                    uint32_t b0 = vr[ rot      & 127];
                    uint32_t b1 = vr[(rot + 4) & 127];
                    float* D = (nv==0) ? D0 : (nv==1) ? D1 : (nv==2) ? D2 : D3;
                    mma_f16(D[0], D[1], D[2], D[3], a0, a1, a2, a3, b0, b1);
                }
            }
        }

        float s0 = s0a + s0b, s1 = s1a + s1b;
        s0 += __shfl_xor_sync(0xffffffffu, s0, 1);
        s0 += __shfl_xor_sync(0xffffffffu, s0, 2);
        s1 += __shfl_xor_sync(0xffffffffu, s1, 1);
        s1 += __shfl_xor_sync(0xffffffffu, s1, 2);
        float inv0 = 1.f / s0, inv1 = 1.f / s1;

        // epilogue: gate + store half2
        uint32_t* ou = (uint32_t*)g_oh;
        #pragma unroll
        for (int nv = 0; nv < 4; nv++) {
            const float* D = (nv==0) ? D0 : (nv==1) ? D1 : (nv==2) ? D2 : D3;
            float2 ga = h2f2(ghu[ia*16 + nv*4 + tid]);
            float2 gb = h2f2(ghu[ib*16 + nv*4 + tid]);
            int cu = (h*CC)/2 + nv*4 + tid;
            ou[(size_t)(s*II + ia)*(HH*CC/2) + cu] = packh2(D[0]*inv0*ga.x, D[1]*inv0*ga.y);
            ou[(size_t)(s*II + ib)*(HH*CC/2) + cu] = packh2(D[2]*inv1*gb.x, D[3]*inv1*gb.y);
        }
    }
}

// ---------------------------------------------------------------------------
// Kernel D: out = o @ wo + bo via fp16 m16n8k16. M-tile=64, 128 threads.
//   o tile batched into registers FIRST; wT staging work hides the latency.
// ---------------------------------------------------------------------------
#define OUT_SMEM_BYTES ((64*132 + 32*128 + 32) * 4)
__global__ __launch_bounds__(128, 4) void outproj_kernel(
    const float* __restrict__ wo, const float* __restrict__ bo,
    float* __restrict__ out)
{
    extern __shared__ uint32_t smu[];
    uint32_t* oS = smu;                 // [64][132]
    uint32_t* wT = oS + 64*132;         // [32][128]
    float*   sbo = (float*)(wT + 32*128);

    int t = threadIdx.x, lane = t & 31, w = t >> 5;
    int g = lane >> 2, tid = lane & 3;
    int r0 = blockIdx.x * 64;

    // 1) issue all o loads (16 uint4 per thread, coalesced) -- they fly
    //    while the wT staging below executes.
    uint4 ov[16];
    const uint4* op = (const uint4*)((const uint32_t*)g_oh + (size_t)r0*(HH*CC/2));
    #pragma unroll
    for (int i = 0; i < 16; i++) ov[i] = op[t + 128*i];

    // 2) independent work: stage wo transposed + cvt
    for (int idx = t; idx < 4096; idx += 128) {
        int u = idx >> 5, c = idx & 31;
        float w0 = wo[(2*u)*32 + c];
        float w1 = wo[(2*u+1)*32 + c];
        wT[c*128 + ((u + 4*c) & 127)] = packh2(w0, w1);
    }
    if (t < 32) sbo[t] = bo[t];

    // 3) store o tiles to smem
    #pragma unroll
    for (int i = 0; i < 16; i++) {
        int idx = t + 128*i;
        int r = idx >> 5, u4 = idx & 31;
        *(uint4*)&oS[r*132 + 4*u4] = ov[i];
    }
    __syncthreads();

    int iw = w*16;
    float D0[4], D1[4], D2[4], D3[4];
    #pragma unroll
    for (int k = 0; k < 4; k++) { D0[k]=0.f; D1[k]=0.f; D2[k]=0.f; D3[k]=0.f; }

    #pragma unroll 4
    for (int kt = 0; kt < 16; kt++) {
        int u = 8*kt + tid;
        uint32_t a0 = oS[(iw+g  )*132 + u];
        uint32_t a1 = oS[(iw+g+8)*132 + u];
        uint32_t a2 = oS[(iw+g  )*132 + u + 4];
        uint32_t a3 = oS[(iw+g+8)*132 + u + 4];
        #pragma unroll
        for (int nt = 0; nt < 4; nt++) {
            int c = nt*8 + g;
            const uint32_t* wr = wT + c*128;
            int rot = 4*c + 8*kt + tid;
            uint32_t b0 = wr[ rot      & 127];
            uint32_t b1 = wr[(rot + 4) & 127];
            float* D = (nt == 0) ? D0 : (nt == 1) ? D1 : (nt == 2) ? D2 : D3;
            mma_f16(D[0], D[1], D[2], D[3], a0, a1, a2, a3, b0, b1);
        }
    }

    int ra = r0 + iw + g, rb = r0 + iw + g + 8;
    #pragma unroll
    for (int nt = 0; nt < 4; nt++) {
        const float* D = (nt == 0) ? D0 : (nt == 1) ? D1 : (nt == 2) ? D2 : D3;
        int c = nt*8 + 2*tid;
        float2 bb = make_float2(sbo[c], sbo[c+1]);
        *(float2*)&out[(size_t)ra*CC + c] = make_float2(D[0] + bb.x, D[1] + bb.y);
        *(float2*)&out[(size_t)rb*CC + c] = make_float2(D[2] + bb.x, D[3] + bb.y);
    }
}

// ---------------------------------------------------------------------------
extern "C" void kernel_launch(void* const* d_in, const int* in_sizes, int n_in,
                              void* d_out, int out_size)
{
    const float* m         = (const float*)d_in[0];
    const float* z         = (const float*)d_in[1];
    const float* ln_scale  = (const float*)d_in[2];
    const float* ln_bias   = (const float*)d_in[3];
    const float* lnb_scale = (const float*)d_in[4];
    const float* lnb_bias  = (const float*)d_in[5];
    const float* wq        = (const float*)d_in[6];
    const float* wk        = (const float*)d_in[7];
    const float* wv        = (const float*)d_in[8];
    const float* wb        = (const float*)d_in[9];
    const float* wg        = (const float*)d_in[10];
    const float* wo        = (const float*)d_in[11];
    const float* bo        = (const float*)d_in[12];
    float* out = (float*)d_out;

    cudaFuncSetAttribute(proj_kernel, cudaFuncAttributeMaxDynamicSharedMemorySize,
                         PROJ_SM_WORDS * 4);
    cudaFuncSetAttribute(outproj_kernel, cudaFuncAttributeMaxDynamicSharedMemorySize,
                         OUT_SMEM_BYTES);

    bias_kernel<<<ZROW/256, 256>>>(z, lnb_scale, lnb_bias, wb);
    proj_kernel<<<(NROW/128)*2, 256, PROJ_SM_WORDS*4>>>(m, ln_scale, ln_bias, wq, wk, wv, wg);
    attn_kernel<<<SS*HH, 256>>>();
    outproj_kernel<<<NROW/64, 128, OUT_SMEM_BYTES>>>(wo, bo, out);
}

// round 10
// speedup vs baseline: 1.0370x; 1.0029x over previous
#include <cuda_runtime.h>
#include <cuda_fp16.h>
#include <math.h>
#include <stdint.h>

#define CC 32
#define HH 8
#define SS 128
#define II 256
#define JJ 256
#define NROW (SS*II)      // 32768 m-rows
#define ZROW (II*JJ)      // 65536 z-rows

#define LOG2E 1.44269504088896f

// Scratch (allocation-free): zero-init device globals.
__device__ __half g_qh[SS*HH*II*CC];  // [s][h][i][c], pre-scaled by 32^-0.5 * log2e
__device__ __half g_kh[SS*HH*II*CC];
__device__ __half g_vh[SS*HH*II*CC];
__device__ __half g_gh[SS*HH*II*CC];  // sigmoid(gate)
__device__ float  g_bf[HH*ZROW];      // [h][i][j] = b*log2e - 8*log2e
__device__ __half g_oh[NROW*HH*CC];   // [s][i][h*32+c], half2-packed

// ---------------------------------------------------------------------------
// helpers
// ---------------------------------------------------------------------------
__device__ __forceinline__ uint32_t packh2(float a, float b) {
    __half2 h = __floats2half2_rn(a, b);
    return *reinterpret_cast<uint32_t*>(&h);
}
__device__ __forceinline__ float2 h2f2(uint32_t u) {
    __half2 h = *reinterpret_cast<__half2*>(&u);
    return __half22float2(h);
}
__device__ __forceinline__ float ex2(float x) {
    float y;
    asm("ex2.approx.ftz.f32 %0, %1;" : "=f"(y) : "f"(x));
    return y;
}
__device__ __forceinline__ void mma_f16(
    float& d0, float& d1, float& d2, float& d3,
    uint32_t a0, uint32_t a1, uint32_t a2, uint32_t a3,
    uint32_t b0, uint32_t b1)
{
    asm volatile(
        "mma.sync.aligned.m16n8k16.row.col.f32.f16.f16.f32 "
        "{%0,%1,%2,%3},{%4,%5,%6,%7},{%8,%9},{%0,%1,%2,%3};"
        : "+f"(d0), "+f"(d1), "+f"(d2), "+f"(d3)
        : "r"(a0), "r"(a1), "r"(a2), "r"(a3), "r"(b0), "r"(b1));
}

// ---------------------------------------------------------------------------
// Kernel B (fused): blocks [0,512) = q/k/v/gate projection via fp16 mma;
// blocks [512,768) = pair-bias kernel (layernorm(z)@wb) — runs on FMA/MUFU
// pipes and hides under proj's saturated tensor dispatch.
// ---------------------------------------------------------------------------
#define PROJ_SM_WORDS (8192 + 2048 + 128*33 + 64)
__global__ __launch_bounds__(256, 3) void proj_kernel(
    const float* __restrict__ m, const float* __restrict__ lns,
    const float* __restrict__ lnb,
    const float* __restrict__ wq, const float* __restrict__ wk,
    const float* __restrict__ wv, const float* __restrict__ wg,
    const float* __restrict__ z, const float* __restrict__ lnbs,
    const float* __restrict__ lnbb, const float* __restrict__ wb)
{
    extern __shared__ uint32_t psm[];
    int t = threadIdx.x;

    if (blockIdx.x >= 512) {
        // ---------------- bias path ----------------
        float* swb = (float*)psm;            // [256]
        float* sbs = swb + CC*HH;            // [32]
        float* sbb = sbs + CC;               // [32]
        if (t < CC*HH) swb[t] = wb[t];
        if (t < CC) { sbs[t] = lnbs[t]; sbb[t] = lnbb[t]; }
        __syncthreads();

        int row = (blockIdx.x - 512) * 256 + t;      // row = i*256 + j
        const float4* zp = (const float4*)(z + (size_t)row * CC);
        float x[CC];
        #pragma unroll
        for (int q4 = 0; q4 < CC/4; q4++) {
            float4 f = zp[q4];
            x[4*q4+0]=f.x; x[4*q4+1]=f.y; x[4*q4+2]=f.z; x[4*q4+3]=f.w;
        }
        float mu = 0.f;
        #pragma unroll
        for (int c = 0; c < CC; c++) mu += x[c];
        mu *= (1.f/CC);
        float var = 0.f;
        #pragma unroll
        for (int c = 0; c < CC; c++) { float d = x[c]-mu; var += d*d; }
        var *= (1.f/CC);
        float rs = rsqrtf(var + 1e-5f);
        #pragma unroll
        for (int c = 0; c < CC; c++) x[c] = (x[c]-mu)*rs*sbs[c] + sbb[c];

        #pragma unroll
        for (int h = 0; h < HH; h++) {
            float acc = 0.f;
            #pragma unroll
            for (int c = 0; c < CC; c++) acc += x[c] * swb[c*HH + h];
            g_bf[h*ZROW + row] = acc * LOG2E - 8.0f * LOG2E;
        }
        return;
    }

    // ---------------- proj path ----------------
    uint32_t* wS  = psm;                 // [512*16]
    uint32_t* mnS = wS + 8192;           // [128*16]
    float* msF = (float*)(mnS + 2048);   // [128][33]
    float* sls = msF + 128*33;
    float* slb = sls + 32;

    int lane = t & 31, w = t >> 5;
    int g = lane >> 2, tid = lane & 3;
    int mt = blockIdx.x >> 1, nh = blockIdx.x & 1;
    int r0 = mt * 128;
    const float sd = 0.176776695296636893f * LOG2E;   // folded exp2 scale

    for (int idx = t; idx < 8192; idx += 256) {
        int u = idx >> 9, n = idx & 511;
        int gcol = nh*512 + n;
        int tensor = gcol >> 8, nc = gcol & 255;
        const float* wp = (tensor==0) ? wq : (tensor==1) ? wk :
                          (tensor==2) ? wv : wg;
        float sc = (tensor==0) ? sd : 1.f;
        float w0 = wp[(2*u)*256 + nc] * sc;
        float w1 = wp[(2*u+1)*256 + nc] * sc;
        wS[n*16 + ((u + 2*n) & 15)] = packh2(w0, w1);
    }
    if (t < 32) { sls[t] = lns[t]; slb[t] = lnb[t]; }

    const float4* mp = (const float4*)(m + (size_t)r0 * CC);
    for (int idx = t; idx < 1024; idx += 256) {
        int r = idx >> 3, c4 = idx & 7;
        float4 f = mp[idx];
        msF[r*33 + 4*c4+0] = f.x; msF[r*33 + 4*c4+1] = f.y;
        msF[r*33 + 4*c4+2] = f.z; msF[r*33 + 4*c4+3] = f.w;
    }
    __syncthreads();

    if (t < 128) {
        float mu = 0.f;
        #pragma unroll
        for (int c = 0; c < CC; c++) mu += msF[t*33 + c];
        mu *= (1.f/CC);
        float var = 0.f;
        #pragma unroll
        for (int c = 0; c < CC; c++) { float d = msF[t*33+c]-mu; var += d*d; }
        var *= (1.f/CC);
        float rs = rsqrtf(var + 1e-5f);
        #pragma unroll
        for (int c = 0; c < CC; c++)
            msF[t*33 + c] = (msF[t*33+c]-mu)*rs*sls[c] + slb[c];
    }
    __syncthreads();

    for (int idx = t; idx < 2048; idx += 256) {
        int r = idx >> 4, u = idx & 15;
        mnS[r*16 + ((u + 2*r) & 15)] = packh2(msF[r*33 + 2*u], msF[r*33 + 2*u + 1]);
    }
    __syncthreads();

    int iw = w*16, ia = iw + g, ib = ia + 8;
    uint32_t A[2][4];
    #pragma unroll
    for (int kt = 0; kt < 2; kt++) {
        A[kt][0] = mnS[ia*16 + ((8*kt + tid     + 2*ia) & 15)];
        A[kt][1] = mnS[ib*16 + ((8*kt + tid     + 2*ib) & 15)];
        A[kt][2] = mnS[ia*16 + ((8*kt + tid + 4 + 2*ia) & 15)];
        A[kt][3] = mnS[ib*16 + ((8*kt + tid + 4 + 2*ib) & 15)];
    }
    int ra = r0 + ia, rb = r0 + ib;
    int sa = ra >> 8, ia2 = ra & 255;
    int sb = rb >> 8, ib2 = rb & 255;

    #pragma unroll
    for (int t2 = 0; t2 < 2; t2++) {
        int tensor = nh*2 + t2;
        __half* dsth = (tensor==0) ? g_qh : (tensor==1) ? g_kh :
                       (tensor==2) ? g_vh : g_gh;
        uint32_t* du = (uint32_t*)dsth;
        bool is_gate = (tensor == 3);
        #pragma unroll 4
        for (int nt2 = 0; nt2 < 32; nt2++) {
            int nt = t2*32 + nt2;
            int n = nt*8 + g;
            const uint32_t* wr = wS + n*16;
            int rot = 2*n;
            uint32_t b00 = wr[(tid      + rot) & 15];
            uint32_t b01 = wr[(tid + 4  + rot) & 15];
            uint32_t b10 = wr[(tid + 8  + rot) & 15];
            uint32_t b11 = wr[(tid + 12 + rot) & 15];
            float d0=0.f, d1=0.f, d2=0.f, d3=0.f;
            mma_f16(d0,d1,d2,d3, A[0][0],A[0][1],A[0][2],A[0][3], b00,b01);
            mma_f16(d0,d1,d2,d3, A[1][0],A[1][1],A[1][2],A[1][3], b10,b11);
            if (is_gate) {
                d0 = 1.f/(1.f + __expf(-d0));
                d1 = 1.f/(1.f + __expf(-d1));
                d2 = 1.f/(1.f + __expf(-d2));
                d3 = 1.f/(1.f + __expf(-d3));
            }
            int nc8 = (nt*8 + 2*tid) & 255;      // col within tensor
            int h = nc8 >> 5, cu = (nc8 & 31) >> 1;
            du[(size_t)((sa*HH + h)*II + ia2)*16 + cu] = packh2(d0, d1);
            du[(size_t)((sb*HH + h)*II + ib2)*16 + cu] = packh2(d2, d3);
        }
    }
}

// ---------------------------------------------------------------------------
// Kernel C: attention per (s,h); fp16 mma; exp2-domain scores (q pre-scaled by
//   sd*log2e, bias by log2e with -8*log2e folded). 3 CTAs/SM.
// ---------------------------------------------------------------------------
__global__ __launch_bounds__(256, 3) void attn_kernel()
{
    __shared__ uint32_t Ksb[256*16];    // 16 KB
    __shared__ uint32_t Vtb[32*128];    // 16 KB

    int t = threadIdx.x, lane = t & 31, w = t >> 5;
    int g = lane >> 2, tid = lane & 3;
    int h = blockIdx.x & 7, s = blockIdx.x >> 3;
    size_t blk = (size_t)(s*HH + h) * (II*CC/2);   // half2-unit base
    const uint32_t* khu = (const uint32_t*)g_kh + blk;
    const uint16_t* vhu = (const uint16_t*)g_vh + blk*2;
    const uint32_t* qhu = (const uint32_t*)g_qh + blk;
    const uint32_t* ghu = (const uint32_t*)g_gh + blk;
    const float* bfp = g_bf + (size_t)h*ZROW;

    for (int idx = t; idx < 4096; idx += 256) {
        int j = idx >> 4, u = idx & 15;
        Ksb[j*16 + ((u + 2*j) & 15)] = khu[idx];
    }
    for (int idx = t; idx < 4096; idx += 256) {
        int u = idx >> 5, c = idx & 31;
        uint32_t lo = vhu[(2*u)*32 + c];
        uint32_t hi = vhu[(2*u+1)*32 + c];
        Vtb[c*128 + ((u + 4*c) & 127)] = lo | (hi << 16);
    }
    __syncthreads();

    #pragma unroll 1
    for (int round = 0; round < 2; round++) {
        int iw = round*128 + w*16;
        int ia = iw + g, ib = ia + 8;

        uint32_t A[2][4];
        #pragma unroll
        for (int kt = 0; kt < 2; kt++) {
            A[kt][0] = qhu[ia*16 + 8*kt + tid];
            A[kt][1] = qhu[ib*16 + 8*kt + tid];
            A[kt][2] = qhu[ia*16 + 8*kt + tid + 4];
            A[kt][3] = qhu[ib*16 + 8*kt + tid + 4];
        }
        const float2* b0f = (const float2*)(bfp + (size_t)ia*JJ);
        const float2* b1f = (const float2*)(bfp + (size_t)ib*JJ);

        float s0a = 0.f, s0b = 0.f, s1a = 0.f, s1b = 0.f;
        float D0[4], D1[4], D2[4], D3[4];
        #pragma unroll
        for (int k = 0; k < 4; k++) { D0[k]=0.f; D1[k]=0.f; D2[k]=0.f; D3[k]=0.f; }

        #pragma unroll 1
        for (int ch = 0; ch < 4; ch++) {
            int u0 = ch*32;            // float2 unit offset (64 j)
            float S0[16], S1[16];
            // bias (exp2-domain, shift folded) as initial accumulator
            #pragma unroll
            for (int nt = 0; nt < 8; nt++) {
                float2 bf = b0f[u0 + nt*4 + tid];
                S0[2*nt] = bf.x; S0[2*nt+1] = bf.y;
                bf = b1f[u0 + nt*4 + tid];
                S1[2*nt] = bf.x; S1[2*nt+1] = bf.y;
            }
            // QK^T
            #pragma unroll
            for (int nt = 0; nt < 8; nt++) {
                int j = ch*64 + nt*8 + g;
                const uint32_t* kr = Ksb + j*16;
                int rot = 2*j;
                uint32_t b00 = kr[(tid      + rot) & 15];
                uint32_t b01 = kr[(tid + 4  + rot) & 15];
                uint32_t b10 = kr[(tid + 8  + rot) & 15];
                uint32_t b11 = kr[(tid + 12 + rot) & 15];
                mma_f16(S0[2*nt], S0[2*nt+1], S1[2*nt], S1[2*nt+1],
                        A[0][0], A[0][1], A[0][2], A[0][3], b00, b01);
                mma_f16(S0[2*nt], S0[2*nt+1], S1[2*nt], S1[2*nt+1],
                        A[1][0], A[1][1], A[1][2], A[1][3], b10, b11);
            }
            // single-op exp2; pack for AV
            uint32_t h0[8], h1[8];
            #pragma unroll
            for (int nt = 0; nt < 8; nt++) {
                float e0 = ex2(S0[2*nt]);
                float e1 = ex2(S0[2*nt+1]);
                float e2 = ex2(S1[2*nt]);
                float e3 = ex2(S1[2*nt+1]);
                if (nt & 1) { s0b += e0 + e1; s1b += e2 + e3; }
                else        { s0a += e0 + e1; s1a += e2 + e3; }
                h0[nt] = packh2(e0, e1);
                h1[nt] = packh2(e2, e3);
            }
            #pragma unroll
            for (int kt = 0; kt < 4; kt++) {
                uint32_t a0 = h0[2*kt], a1 = h1[2*kt];
                uint32_t a2 = h0[2*kt+1], a3 = h1[2*kt+1];
                int ktg = ch*4 + kt;
                #pragma unroll
                for (int nv = 0; nv < 4; nv++) {
                    int c = nv*8 + g;
                    const uint32_t* vr = Vtb + c*128;
                    int rot = 4*c + 8*ktg + tid;
                    uint32_t b0 = vr[ rot      & 127];
                    uint32_t b1 = vr[(rot + 4) & 127];
                    float* D = (nv==0) ? D0 : (nv==1) ? D1 : (nv==2) ? D2 : D3;
                    mma_f16(D[0], D[1], D[2], D[3], a0, a1, a2, a3, b0, b1);
                }
            }
        }

        float s0 = s0a + s0b, s1 = s1a + s1b;
        s0 += __shfl_xor_sync(0xffffffffu, s0, 1);
        s0 += __shfl_xor_sync(0xffffffffu, s0, 2);
        s1 += __shfl_xor_sync(0xffffffffu, s1, 1);
        s1 += __shfl_xor_sync(0xffffffffu, s1, 2);
        float inv0 = 1.f / s0, inv1 = 1.f / s1;

        // epilogue: gate + store half2
        uint32_t* ou = (uint32_t*)g_oh;
        #pragma unroll
        for (int nv = 0; nv < 4; nv++) {
            const float* D = (nv==0) ? D0 : (nv==1) ? D1 : (nv==2) ? D2 : D3;
            float2 ga = h2f2(ghu[ia*16 + nv*4 + tid]);
            float2 gb = h2f2(ghu[ib*16 + nv*4 + tid]);
            int cu = (h*CC)/2 + nv*4 + tid;
            ou[(size_t)(s*II + ia)*(HH*CC/2) + cu] = packh2(D[0]*inv0*ga.x, D[1]*inv0*ga.y);
            ou[(size_t)(s*II + ib)*(HH*CC/2) + cu] = packh2(D[2]*inv1*gb.x, D[3]*inv1*gb.y);
        }
    }
}

// ---------------------------------------------------------------------------
// Kernel D: out = o @ wo + bo via fp16 m16n8k16. M-tile=64, 128 threads.
//   o tile batched into registers FIRST; wT staging work hides the latency.
// ---------------------------------------------------------------------------
#define OUT_SMEM_BYTES ((64*132 + 32*128 + 32) * 4)
__global__ __launch_bounds__(128, 4) void outproj_kernel(
    const float* __restrict__ wo, const float* __restrict__ bo,
    float* __restrict__ out)
{
    extern __shared__ uint32_t smu[];
    uint32_t* oS = smu;                 // [64][132]
    uint32_t* wT = oS + 64*132;         // [32][128]
    float*   sbo = (float*)(wT + 32*128);

    int t = threadIdx.x, lane = t & 31, w = t >> 5;
    int g = lane >> 2, tid = lane & 3;
    int r0 = blockIdx.x * 64;

    // 1) issue all o loads (16 uint4 per thread, coalesced)
    uint4 ov[16];
    const uint4* op = (const uint4*)((const uint32_t*)g_oh + (size_t)r0*(HH*CC/2));
    #pragma unroll
    for (int i = 0; i < 16; i++) ov[i] = op[t + 128*i];

    // 2) independent work: stage wo transposed + cvt
    for (int idx = t; idx < 4096; idx += 128) {
        int u = idx >> 5, c = idx & 31;
        float w0 = wo[(2*u)*32 + c];
        float w1 = wo[(2*u+1)*32 + c];
        wT[c*128 + ((u + 4*c) & 127)] = packh2(w0, w1);
    }
    if (t < 32) sbo[t] = bo[t];

    // 3) store o tiles to smem
    #pragma unroll
    for (int i = 0; i < 16; i++) {
        int idx = t + 128*i;
        int r = idx >> 5, u4 = idx & 31;
        *(uint4*)&oS[r*132 + 4*u4] = ov[i];
    }
    __syncthreads();

    int iw = w*16;
    float D0[4], D1[4], D2[4], D3[4];
    #pragma unroll
    for (int k = 0; k < 4; k++) { D0[k]=0.f; D1[k]=0.f; D2[k]=0.f; D3[k]=0.f; }

    #pragma unroll 4
    for (int kt = 0; kt < 16; kt++) {
        int u = 8*kt + tid;
        uint32_t a0 = oS[(iw+g  )*132 + u];
        uint32_t a1 = oS[(iw+g+8)*132 + u];
        uint32_t a2 = oS[(iw+g  )*132 + u + 4];
        uint32_t a3 = oS[(iw+g+8)*132 + u + 4];
        #pragma unroll
        for (int nt = 0; nt < 4; nt++) {
            int c = nt*8 + g;
            const uint32_t* wr = wT + c*128;
            int rot = 4*c + 8*kt + tid;
            uint32_t b0 = wr[ rot      & 127];
            uint32_t b1 = wr[(rot + 4) & 127];
            float* D = (nt == 0) ? D0 : (nt == 1) ? D1 : (nt == 2) ? D2 : D3;
            mma_f16(D[0], D[1], D[2], D[3], a0, a1, a2, a3, b0, b1);
        }
    }

    int ra = r0 + iw + g, rb = r0 + iw + g + 8;
    #pragma unroll
    for (int nt = 0; nt < 4; nt++) {
        const float* D = (nt == 0) ? D0 : (nt == 1) ? D1 : (nt == 2) ? D2 : D3;
        int c = nt*8 + 2*tid;
        float2 bb = make_float2(sbo[c], sbo[c+1]);
        *(float2*)&out[(size_t)ra*CC + c] = make_float2(D[0] + bb.x, D[1] + bb.y);
        *(float2*)&out[(size_t)rb*CC + c] = make_float2(D[2] + bb.x, D[3] + bb.y);
    }
}

// ---------------------------------------------------------------------------
extern "C" void kernel_launch(void* const* d_in, const int* in_sizes, int n_in,
                              void* d_out, int out_size)
{
    const float* m         = (const float*)d_in[0];
    const float* z         = (const float*)d_in[1];
    const float* ln_scale  = (const float*)d_in[2];
    const float* ln_bias   = (const float*)d_in[3];
    const float* lnb_scale = (const float*)d_in[4];
    const float* lnb_bias  = (const float*)d_in[5];
    const float* wq        = (const float*)d_in[6];
    const float* wk        = (const float*)d_in[7];
    const float* wv        = (const float*)d_in[8];
    const float* wb        = (const float*)d_in[9];
    const float* wg        = (const float*)d_in[10];
    const float* wo        = (const float*)d_in[11];
    const float* bo        = (const float*)d_in[12];
    float* out = (float*)d_out;

    cudaFuncSetAttribute(proj_kernel, cudaFuncAttributeMaxDynamicSharedMemorySize,
                         PROJ_SM_WORDS * 4);
    cudaFuncSetAttribute(outproj_kernel, cudaFuncAttributeMaxDynamicSharedMemorySize,
                         OUT_SMEM_BYTES);

    // Fused proj (blocks 0..511) + bias (blocks 512..767)
    proj_kernel<<<768, 256, PROJ_SM_WORDS*4>>>(m, ln_scale, ln_bias,
                                               wq, wk, wv, wg,
                                               z, lnb_scale, lnb_bias, wb);
    attn_kernel<<<SS*HH, 256>>>();
    outproj_kernel<<<NROW/64, 128, OUT_SMEM_BYTES>>>(wo, bo, out);
}

// round 11
// speedup vs baseline: 1.0711x; 1.0328x over previous
#include <cuda_runtime.h>
#include <cuda_fp16.h>
#include <math.h>
#include <stdint.h>

#define CC 32
#define HH 8
#define SS 128
#define II 256
#define JJ 256
#define NROW (SS*II)      // 32768 m-rows
#define ZROW (II*JJ)      // 65536 z-rows

#define LOG2E 1.44269504088896f

// Scratch (allocation-free): zero-init device globals.
__device__ __half g_qh[SS*HH*II*CC];  // [s][h][i][c], pre-scaled by 32^-0.5 * log2e
__device__ __half g_kh[SS*HH*II*CC];
__device__ __half g_vh[SS*HH*II*CC];
__device__ __half g_gh[SS*HH*II*CC];  // sigmoid(gate)
__device__ float  g_bf[HH*ZROW];      // [h][i][j] = b*log2e - 8*log2e
__device__ __half g_oh[NROW*HH*CC];   // [s][i][h*32+c], half2-packed

// ---------------------------------------------------------------------------
// helpers
// ---------------------------------------------------------------------------
__device__ __forceinline__ uint32_t packh2(float a, float b) {
    __half2 h = __floats2half2_rn(a, b);
    return *reinterpret_cast<uint32_t*>(&h);
}
__device__ __forceinline__ float2 h2f2(uint32_t u) {
    __half2 h = *reinterpret_cast<__half2*>(&u);
    return __half22float2(h);
}
__device__ __forceinline__ float ex2(float x) {
    float y;
    asm("ex2.approx.ftz.f32 %0, %1;" : "=f"(y) : "f"(x));
    return y;
}
__device__ __forceinline__ void mma_f16(
    float& d0, float& d1, float& d2, float& d3,
    uint32_t a0, uint32_t a1, uint32_t a2, uint32_t a3,
    uint32_t b0, uint32_t b1)
{
    asm volatile(
        "mma.sync.aligned.m16n8k16.row.col.f32.f16.f16.f32 "
        "{%0,%1,%2,%3},{%4,%5,%6,%7},{%8,%9},{%0,%1,%2,%3};"
        : "+f"(d0), "+f"(d1), "+f"(d2), "+f"(d3)
        : "r"(a0), "r"(a1), "r"(a2), "r"(a3), "r"(b0), "r"(b1));
}

// ---------------------------------------------------------------------------
// Kernel B (fused): blocks [0,512) = q/k/v/gate projection via fp16 mma with
// smem-bounced coalesced stores; blocks [512,768) = pair-bias kernel.
// smem words: wS [0,8192) | mnS [8192,10240) | msF/staging [10240,14464) |
//             sls/slb [14464,14528)
// ---------------------------------------------------------------------------
#define PROJ_SM_WORDS (8192 + 2048 + 4224 + 64)
__global__ __launch_bounds__(256, 3) void proj_kernel(
    const float* __restrict__ m, const float* __restrict__ lns,
    const float* __restrict__ lnb,
    const float* __restrict__ wq, const float* __restrict__ wk,
    const float* __restrict__ wv, const float* __restrict__ wg,
    const float* __restrict__ z, const float* __restrict__ lnbs,
    const float* __restrict__ lnbb, const float* __restrict__ wb)
{
    extern __shared__ uint32_t psm[];
    int t = threadIdx.x;

    if (blockIdx.x >= 512) {
        // ---------------- bias path ----------------
        float* swb = (float*)psm;            // [256]
        float* sbs = swb + CC*HH;            // [32]
        float* sbb = sbs + CC;               // [32]
        if (t < CC*HH) swb[t] = wb[t];
        if (t < CC) { sbs[t] = lnbs[t]; sbb[t] = lnbb[t]; }
        __syncthreads();

        int row = (blockIdx.x - 512) * 256 + t;      // row = i*256 + j
        const float4* zp = (const float4*)(z + (size_t)row * CC);
        float x[CC];
        #pragma unroll
        for (int q4 = 0; q4 < CC/4; q4++) {
            float4 f = zp[q4];
            x[4*q4+0]=f.x; x[4*q4+1]=f.y; x[4*q4+2]=f.z; x[4*q4+3]=f.w;
        }
        float mu = 0.f;
        #pragma unroll
        for (int c = 0; c < CC; c++) mu += x[c];
        mu *= (1.f/CC);
        float var = 0.f;
        #pragma unroll
        for (int c = 0; c < CC; c++) { float d = x[c]-mu; var += d*d; }
        var *= (1.f/CC);
        float rs = rsqrtf(var + 1e-5f);
        #pragma unroll
        for (int c = 0; c < CC; c++) x[c] = (x[c]-mu)*rs*sbs[c] + sbb[c];

        #pragma unroll
        for (int h = 0; h < HH; h++) {
            float acc = 0.f;
            #pragma unroll
            for (int c = 0; c < CC; c++) acc += x[c] * swb[c*HH + h];
            g_bf[h*ZROW + row] = acc * LOG2E - 8.0f * LOG2E;
        }
        return;
    }

    // ---------------- proj path ----------------
    uint32_t* wS  = psm;                 // [512*16]
    uint32_t* mnS = wS + 8192;           // [128*16]
    float* msF = (float*)(mnS + 2048);   // [128][33] -> reused as store staging
    float* sls = msF + 128*33;
    float* slb = sls + 32;

    int lane = t & 31, w = t >> 5;
    int g = lane >> 2, tid = lane & 3;
    int mt = blockIdx.x >> 1, nh = blockIdx.x & 1;
    int r0 = mt * 128;
    const float sd = 0.176776695296636893f * LOG2E;   // folded exp2 scale

    for (int idx = t; idx < 8192; idx += 256) {
        int u = idx >> 9, n = idx & 511;
        int gcol = nh*512 + n;
        int tensor = gcol >> 8, nc = gcol & 255;
        const float* wp = (tensor==0) ? wq : (tensor==1) ? wk :
                          (tensor==2) ? wv : wg;
        float sc = (tensor==0) ? sd : 1.f;
        float w0 = wp[(2*u)*256 + nc] * sc;
        float w1 = wp[(2*u+1)*256 + nc] * sc;
        wS[n*16 + ((u + 2*n) & 15)] = packh2(w0, w1);
    }
    if (t < 32) { sls[t] = lns[t]; slb[t] = lnb[t]; }

    const float4* mp = (const float4*)(m + (size_t)r0 * CC);
    for (int idx = t; idx < 1024; idx += 256) {
        int r = idx >> 3, c4 = idx & 7;
        float4 f = mp[idx];
        msF[r*33 + 4*c4+0] = f.x; msF[r*33 + 4*c4+1] = f.y;
        msF[r*33 + 4*c4+2] = f.z; msF[r*33 + 4*c4+3] = f.w;
    }
    __syncthreads();

    if (t < 128) {
        float mu = 0.f;
        #pragma unroll
        for (int c = 0; c < CC; c++) mu += msF[t*33 + c];
        mu *= (1.f/CC);
        float var = 0.f;
        #pragma unroll
        for (int c = 0; c < CC; c++) { float d = msF[t*33+c]-mu; var += d*d; }
        var *= (1.f/CC);
        float rs = rsqrtf(var + 1e-5f);
        #pragma unroll
        for (int c = 0; c < CC; c++)
            msF[t*33 + c] = (msF[t*33+c]-mu)*rs*sls[c] + slb[c];
    }
    __syncthreads();

    for (int idx = t; idx < 2048; idx += 256) {
        int r = idx >> 4, u = idx & 15;
        mnS[r*16 + ((u + 2*r) & 15)] = packh2(msF[r*33 + 2*u], msF[r*33 + 2*u + 1]);
    }
    __syncthreads();   // msF now dead -> reuse as per-warp store staging

    int iw = w*16, ia = iw + g, ib = ia + 8;
    uint32_t A[2][4];
    #pragma unroll
    for (int kt = 0; kt < 2; kt++) {
        A[kt][0] = mnS[ia*16 + ((8*kt + tid     + 2*ia) & 15)];
        A[kt][1] = mnS[ib*16 + ((8*kt + tid     + 2*ib) & 15)];
        A[kt][2] = mnS[ia*16 + ((8*kt + tid + 4 + 2*ia) & 15)];
        A[kt][3] = mnS[ib*16 + ((8*kt + tid + 4 + 2*ib) & 15)];
    }

    // per-warp staging: 16 rows x stride 20 words (conflict-free, 16B-aligned)
    uint32_t* stG = (uint32_t*)msF + w*320;
    const uint32_t* stR = stG + (lane >> 1)*20 + (lane & 1)*4;
    // this thread's global output row (for the coalesced store phase)
    int gr = r0 + iw + (lane >> 1);
    size_t rowbase = ((size_t)((gr >> 8)*HH)*II + (gr & 255))*16;   // + h*II*16

    #pragma unroll
    for (int t2 = 0; t2 < 2; t2++) {
        int tensor = nh*2 + t2;
        __half* dsth = (tensor==0) ? g_qh : (tensor==1) ? g_kh :
                       (tensor==2) ? g_vh : g_gh;
        uint32_t* du = (uint32_t*)dsth;
        bool is_gate = (tensor == 3);

        #pragma unroll 2
        for (int hh = 0; hh < 8; hh++) {
            #pragma unroll
            for (int nt4 = 0; nt4 < 4; nt4++) {
                int nt = t2*32 + hh*4 + nt4;
                int n = nt*8 + g;
                const uint32_t* wr = wS + n*16;
                int rot = 2*n;
                uint32_t b00 = wr[(tid      + rot) & 15];
                uint32_t b01 = wr[(tid + 4  + rot) & 15];
                uint32_t b10 = wr[(tid + 8  + rot) & 15];
                uint32_t b11 = wr[(tid + 12 + rot) & 15];
                float d0=0.f, d1=0.f, d2=0.f, d3=0.f;
                mma_f16(d0,d1,d2,d3, A[0][0],A[0][1],A[0][2],A[0][3], b00,b01);
                mma_f16(d0,d1,d2,d3, A[1][0],A[1][1],A[1][2],A[1][3], b10,b11);
                if (is_gate) {
                    d0 = 1.f/(1.f + __expf(-d0));
                    d1 = 1.f/(1.f + __expf(-d1));
                    d2 = 1.f/(1.f + __expf(-d2));
                    d3 = 1.f/(1.f + __expf(-d3));
                }
                stG[ g     *20 + nt4*4 + tid] = packh2(d0, d1);
                stG[(g + 8)*20 + nt4*4 + tid] = packh2(d2, d3);
            }
            __syncwarp();
            uint4 v0 = *(const uint4*)(stR);
            uint4 v1 = *(const uint4*)(stR + 8);
            uint32_t* drow = du + rowbase + (size_t)hh*(II*16);
            *(uint4*)(drow + (lane & 1)*4)     = v0;
            *(uint4*)(drow + 8 + (lane & 1)*4) = v1;
            __syncwarp();
        }
    }
}

// ---------------------------------------------------------------------------
// Kernel C: attention per (s,h); fp16 mma; exp2-domain scores (q pre-scaled by
//   sd*log2e, bias by log2e with -8*log2e folded). 3 CTAs/SM.
// ---------------------------------------------------------------------------
__global__ __launch_bounds__(256, 3) void attn_kernel()
{
    __shared__ uint32_t Ksb[256*16];    // 16 KB
    __shared__ uint32_t Vtb[32*128];    // 16 KB

    int t = threadIdx.x, lane = t & 31, w = t >> 5;
    int g = lane >> 2, tid = lane & 3;
    int h = blockIdx.x & 7, s = blockIdx.x >> 3;
    size_t blk = (size_t)(s*HH + h) * (II*CC/2);   // half2-unit base
    const uint32_t* khu = (const uint32_t*)g_kh + blk;
    const uint16_t* vhu = (const uint16_t*)g_vh + blk*2;
    const uint32_t* qhu = (const uint32_t*)g_qh + blk;
    const uint32_t* ghu = (const uint32_t*)g_gh + blk;
    const float* bfp = g_bf + (size_t)h*ZROW;

    for (int idx = t; idx < 4096; idx += 256) {
        int j = idx >> 4, u = idx & 15;
        Ksb[j*16 + ((u + 2*j) & 15)] = khu[idx];
    }
    for (int idx = t; idx < 4096; idx += 256) {
        int u = idx >> 5, c = idx & 31;
        uint32_t lo = vhu[(2*u)*32 + c];
        uint32_t hi = vhu[(2*u+1)*32 + c];
        Vtb[c*128 + ((u + 4*c) & 127)] = lo | (hi << 16);
    }
    __syncthreads();

    #pragma unroll 1
    for (int round = 0; round < 2; round++) {
        int iw = round*128 + w*16;
        int ia = iw + g, ib = ia + 8;

        uint32_t A[2][4];
        #pragma unroll
        for (int kt = 0; kt < 2; kt++) {
            A[kt][0] = qhu[ia*16 + 8*kt + tid];
            A[kt][1] = qhu[ib*16 + 8*kt + tid];
            A[kt][2] = qhu[ia*16 + 8*kt + tid + 4];
            A[kt][3] = qhu[ib*16 + 8*kt + tid + 4];
        }
        const float2* b0f = (const float2*)(bfp + (size_t)ia*JJ);
        const float2* b1f = (const float2*)(bfp + (size_t)ib*JJ);

        float s0a = 0.f, s0b = 0.f, s1a = 0.f, s1b = 0.f;
        float D0[4], D1[4], D2[4], D3[4];
        #pragma unroll
        for (int k = 0; k < 4; k++) { D0[k]=0.f; D1[k]=0.f; D2[k]=0.f; D3[k]=0.f; }

        #pragma unroll 1
        for (int ch = 0; ch < 4; ch++) {
            int u0 = ch*32;            // float2 unit offset (64 j)
            float S0[16], S1[16];
            // bias (exp2-domain, shift folded) as initial accumulator
            #pragma unroll
            for (int nt = 0; nt < 8; nt++) {
                float2 bf = b0f[u0 + nt*4 + tid];
                S0[2*nt] = bf.x; S0[2*nt+1] = bf.y;
                bf = b1f[u0 + nt*4 + tid];
                S1[2*nt] = bf.x; S1[2*nt+1] = bf.y;
            }
            // QK^T
            #pragma unroll
            for (int nt = 0; nt < 8; nt++) {
                int j = ch*64 + nt*8 + g;
                const uint32_t* kr = Ksb + j*16;
                int rot = 2*j;
                uint32_t b00 = kr[(tid      + rot) & 15];
                uint32_t b01 = kr[(tid + 4  + rot) & 15];
                uint32_t b10 = kr[(tid + 8  + rot) & 15];
                uint32_t b11 = kr[(tid + 12 + rot) & 15];
                mma_f16(S0[2*nt], S0[2*nt+1], S1[2*nt], S1[2*nt+1],
                        A[0][0], A[0][1], A[0][2], A[0][3], b00, b01);
                mma_f16(S0[2*nt], S0[2*nt+1], S1[2*nt], S1[2*nt+1],
                        A[1][0], A[1][1], A[1][2], A[1][3], b10, b11);
            }
            // single-op exp2; pack for AV
            uint32_t h0[8], h1[8];
            #pragma unroll
            for (int nt = 0; nt < 8; nt++) {
                float e0 = ex2(S0[2*nt]);
                float e1 = ex2(S0[2*nt+1]);
                float e2 = ex2(S1[2*nt]);
                float e3 = ex2(S1[2*nt+1]);
                if (nt & 1) { s0b += e0 + e1; s1b += e2 + e3; }
                else        { s0a += e0 + e1; s1a += e2 + e3; }
                h0[nt] = packh2(e0, e1);
                h1[nt] = packh2(e2, e3);
            }
            #pragma unroll
            for (int kt = 0; kt < 4; kt++) {
                uint32_t a0 = h0[2*kt], a1 = h1[2*kt];
                uint32_t a2 = h0[2*kt+1], a3 = h1[2*kt+1];
                int ktg = ch*4 + kt;
                #pragma unroll
                for (int nv = 0; nv < 4; nv++) {
                    int c = nv*8 + g;
                    const uint32_t* vr = Vtb + c*128;
                    int rot = 4*c + 8*ktg + tid;
                    uint32_t b0 = vr[ rot      & 127];
                    uint32_t b1 = vr[(rot + 4) & 127];
                    float* D = (nv==0) ? D0 : (nv==1) ? D1 : (nv==2) ? D2 : D3;
                    mma_f16(D[0], D[1], D[2], D[3], a0, a1, a2, a3, b0, b1);
                }
            }
        }

        float s0 = s0a + s0b, s1 = s1a + s1b;
        s0 += __shfl_xor_sync(0xffffffffu, s0, 1);
        s0 += __shfl_xor_sync(0xffffffffu, s0, 2);
        s1 += __shfl_xor_sync(0xffffffffu, s1, 1);
        s1 += __shfl_xor_sync(0xffffffffu, s1, 2);
        float inv0 = 1.f / s0, inv1 = 1.f / s1;

        // epilogue: gate + store half2
        uint32_t* ou = (uint32_t*)g_oh;
        #pragma unroll
        for (int nv = 0; nv < 4; nv++) {
            const float* D = (nv==0) ? D0 : (nv==1) ? D1 : (nv==2) ? D2 : D3;
            float2 ga = h2f2(ghu[ia*16 + nv*4 + tid]);
            float2 gb = h2f2(ghu[ib*16 + nv*4 + tid]);
            int cu = (h*CC)/2 + nv*4 + tid;
            ou[(size_t)(s*II + ia)*(HH*CC/2) + cu] = packh2(D[0]*inv0*ga.x, D[1]*inv0*ga.y);
            ou[(size_t)(s*II + ib)*(HH*CC/2) + cu] = packh2(D[2]*inv1*gb.x, D[3]*inv1*gb.y);
        }
    }
}

// ---------------------------------------------------------------------------
// Kernel D: out = o @ wo + bo via fp16 m16n8k16. M-tile=64, 128 threads.
//   o tile batched into registers FIRST; wT staging work hides the latency.
// ---------------------------------------------------------------------------
#define OUT_SMEM_BYTES ((64*132 + 32*128 + 32) * 4)
__global__ __launch_bounds__(128, 4) void outproj_kernel(
    const float* __restrict__ wo, const float* __restrict__ bo,
    float* __restrict__ out)
{
    extern __shared__ uint32_t smu[];
    uint32_t* oS = smu;                 // [64][132]
    uint32_t* wT = oS + 64*132;         // [32][128]
    float*   sbo = (float*)(wT + 32*128);

    int t = threadIdx.x, lane = t & 31, w = t >> 5;
    int g = lane >> 2, tid = lane & 3;
    int r0 = blockIdx.x * 64;

    // 1) issue all o loads (16 uint4 per thread, coalesced)
    uint4 ov[16];
    const uint4* op = (const uint4*)((const uint32_t*)g_oh + (size_t)r0*(HH*CC/2));
    #pragma unroll
    for (int i = 0; i < 16; i++) ov[i] = op[t + 128*i];

    // 2) independent work: stage wo transposed + cvt
    for (int idx = t; idx < 4096; idx += 128) {
        int u = idx >> 5, c = idx & 31;
        float w0 = wo[(2*u)*32 + c];
        float w1 = wo[(2*u+1)*32 + c];
        wT[c*128 + ((u + 4*c) & 127)] = packh2(w0, w1);
    }
    if (t < 32) sbo[t] = bo[t];

    // 3) store o tiles to smem
    #pragma unroll
    for (int i = 0; i < 16; i++) {
        int idx = t + 128*i;
        int r = idx >> 5, u4 = idx & 31;
        *(uint4*)&oS[r*132 + 4*u4] = ov[i];
    }
    __syncthreads();

    int iw = w*16;
    float D0[4], D1[4], D2[4], D3[4];
    #pragma unroll
    for (int k = 0; k < 4; k++) { D0[k]=0.f; D1[k]=0.f; D2[k]=0.f; D3[k]=0.f; }

    #pragma unroll 4
    for (int kt = 0; kt < 16; kt++) {
        int u = 8*kt + tid;
        uint32_t a0 = oS[(iw+g  )*132 + u];
        uint32_t a1 = oS[(iw+g+8)*132 + u];
        uint32_t a2 = oS[(iw+g  )*132 + u + 4];
        uint32_t a3 = oS[(iw+g+8)*132 + u + 4];
        #pragma unroll
        for (int nt = 0; nt < 4; nt++) {
            int c = nt*8 + g;
            const uint32_t* wr = wT + c*128;
            int rot = 4*c + 8*kt + tid;
            uint32_t b0 = wr[ rot      & 127];
            uint32_t b1 = wr[(rot + 4) & 127];
            float* D = (nt == 0) ? D0 : (nt == 1) ? D1 : (nt == 2) ? D2 : D3;
            mma_f16(D[0], D[1], D[2], D[3], a0, a1, a2, a3, b0, b1);
        }
    }

    int ra = r0 + iw + g, rb = r0 + iw + g + 8;
    #pragma unroll
    for (int nt = 0; nt < 4; nt++) {
        const float* D = (nt == 0) ? D0 : (nt == 1) ? D1 : (nt == 2) ? D2 : D3;
        int c = nt*8 + 2*tid;
        float2 bb = make_float2(sbo[c], sbo[c+1]);
        *(float2*)&out[(size_t)ra*CC + c] = make_float2(D[0] + bb.x, D[1] + bb.y);
        *(float2*)&out[(size_t)rb*CC + c] = make_float2(D[2] + bb.x, D[3] + bb.y);
    }
}

// ---------------------------------------------------------------------------
extern "C" void kernel_launch(void* const* d_in, const int* in_sizes, int n_in,
                              void* d_out, int out_size)
{
    const float* m         = (const float*)d_in[0];
    const float* z         = (const float*)d_in[1];
    const float* ln_scale  = (const float*)d_in[2];
    const float* ln_bias   = (const float*)d_in[3];
    const float* lnb_scale = (const float*)d_in[4];
    const float* lnb_bias  = (const float*)d_in[5];
    const float* wq        = (const float*)d_in[6];
    const float* wk        = (const float*)d_in[7];
    const float* wv        = (const float*)d_in[8];
    const float* wb        = (const float*)d_in[9];
    const float* wg        = (const float*)d_in[10];
    const float* wo        = (const float*)d_in[11];
    const float* bo        = (const float*)d_in[12];
    float* out = (float*)d_out;

    cudaFuncSetAttribute(proj_kernel, cudaFuncAttributeMaxDynamicSharedMemorySize,
                         PROJ_SM_WORDS * 4);
    cudaFuncSetAttribute(outproj_kernel, cudaFuncAttributeMaxDynamicSharedMemorySize,
                         OUT_SMEM_BYTES);

    // Fused proj (blocks 0..511) + bias (blocks 512..767)
    proj_kernel<<<768, 256, PROJ_SM_WORDS*4>>>(m, ln_scale, ln_bias,
                                               wq, wk, wv, wg,
                                               z, lnb_scale, lnb_bias, wb);
    attn_kernel<<<SS*HH, 256>>>();
    outproj_kernel<<<NROW/64, 128, OUT_SMEM_BYTES>>>(wo, bo, out);
}

// round 12
// speedup vs baseline: 1.1950x; 1.1157x over previous
#include <cuda_runtime.h>
#include <cuda_fp16.h>
#include <math.h>
#include <stdint.h>

#define CC 32
#define HH 8
#define SS 128
#define II 256
#define JJ 256
#define NROW (SS*II)      // 32768 m-rows
#define ZROW (II*JJ)      // 65536 z-rows

#define LOG2E 1.44269504088896f

// Scratch (allocation-free): zero-init device globals.
__device__ __half g_qh[SS*HH*II*CC];  // [s][h][i][c], pre-scaled by 32^-0.5 * log2e
__device__ __half g_kh[SS*HH*II*CC];
__device__ __half g_vh[SS*HH*II*CC];
__device__ __half g_gh[SS*HH*II*CC];  // sigmoid(gate)
__device__ float  g_bf[HH*ZROW];      // [h][i][j] = b*log2e - 8*log2e
__device__ __half g_oh[NROW*HH*CC];   // [s][i][h*32+c], half2-packed
__device__ uint32_t g_wS[2*8192];     // pre-swizzled half2 weights (proj layout)

// ---------------------------------------------------------------------------
// helpers
// ---------------------------------------------------------------------------
__device__ __forceinline__ uint32_t packh2(float a, float b) {
    __half2 h = __floats2half2_rn(a, b);
    return *reinterpret_cast<uint32_t*>(&h);
}
__device__ __forceinline__ float2 h2f2(uint32_t u) {
    __half2 h = *reinterpret_cast<__half2*>(&u);
    return __half22float2(h);
}
__device__ __forceinline__ float ex2(float x) {
    float y;
    asm("ex2.approx.ftz.f32 %0, %1;" : "=f"(y) : "f"(x));
    return y;
}
__device__ __forceinline__ void mma_f16(
    float& d0, float& d1, float& d2, float& d3,
    uint32_t a0, uint32_t a1, uint32_t a2, uint32_t a3,
    uint32_t b0, uint32_t b1)
{
    asm volatile(
        "mma.sync.aligned.m16n8k16.row.col.f32.f16.f16.f32 "
        "{%0,%1,%2,%3},{%4,%5,%6,%7},{%8,%9},{%0,%1,%2,%3};"
        : "+f"(d0), "+f"(d1), "+f"(d2), "+f"(d3)
        : "r"(a0), "r"(a1), "r"(a2), "r"(a3), "r"(b0), "r"(b1));
}

// ---------------------------------------------------------------------------
// Kernel 0: pre-swizzle q|k|v|g weights into g_wS (proj smem layout).
// ---------------------------------------------------------------------------
__global__ __launch_bounds__(256) void wprep_kernel(
    const float* __restrict__ wq, const float* __restrict__ wk,
    const float* __restrict__ wv, const float* __restrict__ wg)
{
    const float sd = 0.176776695296636893f * LOG2E;
    int gidx = blockIdx.x * 256 + threadIdx.x;     // [0, 16384)
    int nh = gidx >> 13, rest = gidx & 8191;
    int u = rest >> 9, n = rest & 511;
    int gcol = nh*512 + n;
    int tensor = gcol >> 8, nc = gcol & 255;
    const float* wp = (tensor==0) ? wq : (tensor==1) ? wk :
                      (tensor==2) ? wv : wg;
    float sc = (tensor==0) ? sd : 1.f;
    float w0 = wp[(2*u)*256 + nc] * sc;
    float w1 = wp[(2*u+1)*256 + nc] * sc;
    g_wS[nh*8192 + n*16 + ((u + 2*n) & 15)] = packh2(w0, w1);
}

// ---------------------------------------------------------------------------
// Kernel B (fused): blocks [0,512) = q/k/v/gate projection via fp16 mma with
// smem-bounced coalesced stores; blocks [512,768) = pair-bias kernel.
// ---------------------------------------------------------------------------
#define PROJ_SM_WORDS (8192 + 2048 + 4224 + 64)
__global__ __launch_bounds__(256, 3) void proj_kernel(
    const float* __restrict__ m, const float* __restrict__ lns,
    const float* __restrict__ lnb,
    const float* __restrict__ z, const float* __restrict__ lnbs,
    const float* __restrict__ lnbb, const float* __restrict__ wb)
{
    extern __shared__ uint32_t psm[];
    int t = threadIdx.x;

    if (blockIdx.x >= 512) {
        // ---------------- bias path ----------------
        float* swb = (float*)psm;            // [256]
        float* sbs = swb + CC*HH;            // [32]
        float* sbb = sbs + CC;               // [32]
        if (t < CC*HH) swb[t] = wb[t];
        if (t < CC) { sbs[t] = lnbs[t]; sbb[t] = lnbb[t]; }
        __syncthreads();

        int row = (blockIdx.x - 512) * 256 + t;      // row = i*256 + j
        const float4* zp = (const float4*)(z + (size_t)row * CC);
        float x[CC];
        #pragma unroll
        for (int q4 = 0; q4 < CC/4; q4++) {
            float4 f = zp[q4];
            x[4*q4+0]=f.x; x[4*q4+1]=f.y; x[4*q4+2]=f.z; x[4*q4+3]=f.w;
        }
        float mu = 0.f;
        #pragma unroll
        for (int c = 0; c < CC; c++) mu += x[c];
        mu *= (1.f/CC);
        float var = 0.f;
        #pragma unroll
        for (int c = 0; c < CC; c++) { float d = x[c]-mu; var += d*d; }
        var *= (1.f/CC);
        float rs = rsqrtf(var + 1e-5f);
        #pragma unroll
        for (int c = 0; c < CC; c++) x[c] = (x[c]-mu)*rs*sbs[c] + sbb[c];

        #pragma unroll
        for (int h = 0; h < HH; h++) {
            float acc = 0.f;
            #pragma unroll
            for (int c = 0; c < CC; c++) acc += x[c] * swb[c*HH + h];
            g_bf[h*ZROW + row] = acc * LOG2E - 8.0f * LOG2E;
        }
        return;
    }

    // ---------------- proj path ----------------
    uint32_t* wS  = psm;                 // [512*16]
    uint32_t* mnS = wS + 8192;           // [128*16]
    float* msF = (float*)(mnS + 2048);   // [128][33] -> reused as store staging
    float* sls = msF + 128*33;
    float* slb = sls + 32;

    int lane = t & 31, w = t >> 5;
    int g = lane >> 2, tid = lane & 3;
    int mt = blockIdx.x >> 1, nh = blockIdx.x & 1;
    int r0 = mt * 128;

    // weights: straight uint4 copy of pre-swizzled data
    {
        const uint4* wgp = (const uint4*)g_wS + nh*2048;
        uint4* wS4 = (uint4*)wS;
        #pragma unroll
        for (int i = 0; i < 8; i++) wS4[t + 256*i] = wgp[t + 256*i];
    }
    if (t < 32) { sls[t] = lns[t]; slb[t] = lnb[t]; }

    const float4* mp = (const float4*)(m + (size_t)r0 * CC);
    for (int idx = t; idx < 1024; idx += 256) {
        int r = idx >> 3, c4 = idx & 7;
        float4 f = mp[idx];
        msF[r*33 + 4*c4+0] = f.x; msF[r*33 + 4*c4+1] = f.y;
        msF[r*33 + 4*c4+2] = f.z; msF[r*33 + 4*c4+3] = f.w;
    }
    __syncthreads();

    if (t < 128) {
        float mu = 0.f;
        #pragma unroll
        for (int c = 0; c < CC; c++) mu += msF[t*33 + c];
        mu *= (1.f/CC);
        float var = 0.f;
        #pragma unroll
        for (int c = 0; c < CC; c++) { float d = msF[t*33+c]-mu; var += d*d; }
        var *= (1.f/CC);
        float rs = rsqrtf(var + 1e-5f);
        #pragma unroll
        for (int c = 0; c < CC; c++)
            msF[t*33 + c] = (msF[t*33+c]-mu)*rs*sls[c] + slb[c];
    }
    __syncthreads();

    for (int idx = t; idx < 2048; idx += 256) {
        int r = idx >> 4, u = idx & 15;
        mnS[r*16 + ((u + 2*r) & 15)] = packh2(msF[r*33 + 2*u], msF[r*33 + 2*u + 1]);
    }
    __syncthreads();   // msF now dead -> reuse as per-warp store staging

    int iw = w*16, ia = iw + g, ib = ia + 8;
    uint32_t A[2][4];
    #pragma unroll
    for (int kt = 0; kt < 2; kt++) {
        A[kt][0] = mnS[ia*16 + ((8*kt + tid     + 2*ia) & 15)];
        A[kt][1] = mnS[ib*16 + ((8*kt + tid     + 2*ib) & 15)];
        A[kt][2] = mnS[ia*16 + ((8*kt + tid + 4 + 2*ia) & 15)];
        A[kt][3] = mnS[ib*16 + ((8*kt + tid + 4 + 2*ib) & 15)];
    }

    // per-warp staging: 16 rows x stride 20 words.
    // writes: banks 20g+4nt4+tid distinct per phase; reads (row=lane&15,
    // chunk=lane>>4): banks 20r+8q distinct per LDS.128 phase -> conflict-free.
    uint32_t* stG = (uint32_t*)msF + w*320;
    int rr = lane & 15, q = lane >> 4;
    const uint32_t* stR = stG + rr*20 + q*8;
    int gr = r0 + iw + rr;
    size_t rowbase = ((size_t)((gr >> 8)*HH)*II + (gr & 255))*16 + q*8;  // + h*II*16

    #pragma unroll
    for (int t2 = 0; t2 < 2; t2++) {
        int tensor = nh*2 + t2;
        __half* dsth = (tensor==0) ? g_qh : (tensor==1) ? g_kh :
                       (tensor==2) ? g_vh : g_gh;
        uint32_t* du = (uint32_t*)dsth;
        bool is_gate = (tensor == 3);

        #pragma unroll 2
        for (int hh = 0; hh < 8; hh++) {
            #pragma unroll
            for (int nt4 = 0; nt4 < 4; nt4++) {
                int nt = t2*32 + hh*4 + nt4;
                int n = nt*8 + g;
                const uint32_t* wr = wS + n*16;
                int rot = 2*n;
                uint32_t b00 = wr[(tid      + rot) & 15];
                uint32_t b01 = wr[(tid + 4  + rot) & 15];
                uint32_t b10 = wr[(tid + 8  + rot) & 15];
                uint32_t b11 = wr[(tid + 12 + rot) & 15];
                float d0=0.f, d1=0.f, d2=0.f, d3=0.f;
                mma_f16(d0,d1,d2,d3, A[0][0],A[0][1],A[0][2],A[0][3], b00,b01);
                mma_f16(d0,d1,d2,d3, A[1][0],A[1][1],A[1][2],A[1][3], b10,b11);
                if (is_gate) {
                    d0 = 1.f/(1.f + __expf(-d0));
                    d1 = 1.f/(1.f + __expf(-d1));
                    d2 = 1.f/(1.f + __expf(-d2));
                    d3 = 1.f/(1.f + __expf(-d3));
                }
                stG[ g     *20 + nt4*4 + tid] = packh2(d0, d1);
                stG[(g + 8)*20 + nt4*4 + tid] = packh2(d2, d3);
            }
            __syncwarp();
            uint4 v0 = *(const uint4*)(stR);
            uint4 v1 = *(const uint4*)(stR + 4);
            uint32_t* drow = du + rowbase + (size_t)hh*(II*16);
            *(uint4*)(drow)     = v0;
            *(uint4*)(drow + 4) = v1;
            __syncwarp();
        }
    }
}

// ---------------------------------------------------------------------------
// Kernel C: attention per (s,h); fp16 mma; exp2-domain scores (q pre-scaled by
//   sd*log2e, bias by log2e with -8*log2e folded). 3 CTAs/SM.
// ---------------------------------------------------------------------------
__global__ __launch_bounds__(256, 3) void attn_kernel()
{
    __shared__ uint32_t Ksb[256*16];    // 16 KB
    __shared__ uint32_t Vtb[32*128];    // 16 KB

    int t = threadIdx.x, lane = t & 31, w = t >> 5;
    int g = lane >> 2, tid = lane & 3;
    int h = blockIdx.x & 7, s = blockIdx.x >> 3;
    size_t blk = (size_t)(s*HH + h) * (II*CC/2);   // half2-unit base
    const uint32_t* khu = (const uint32_t*)g_kh + blk;
    const uint16_t* vhu = (const uint16_t*)g_vh + blk*2;
    const uint32_t* qhu = (const uint32_t*)g_qh + blk;
    const uint32_t* ghu = (const uint32_t*)g_gh + blk;
    const float* bfp = g_bf + (size_t)h*ZROW;

    for (int idx = t; idx < 4096; idx += 256) {
        int j = idx >> 4, u = idx & 15;
        Ksb[j*16 + ((u + 2*j) & 15)] = khu[idx];
    }
    for (int idx = t; idx < 4096; idx += 256) {
        int u = idx >> 5, c = idx & 31;
        uint32_t lo = vhu[(2*u)*32 + c];
        uint32_t hi = vhu[(2*u+1)*32 + c];
        Vtb[c*128 + ((u + 4*c) & 127)] = lo | (hi << 16);
    }
    __syncthreads();

    #pragma unroll 1
    for (int round = 0; round < 2; round++) {
        int iw = round*128 + w*16;
        int ia = iw + g, ib = ia + 8;

        uint32_t A[2][4];
        #pragma unroll
        for (int kt = 0; kt < 2; kt++) {
            A[kt][0] = qhu[ia*16 + 8*kt + tid];
            A[kt][1] = qhu[ib*16 + 8*kt + tid];
            A[kt][2] = qhu[ia*16 + 8*kt + tid + 4];
            A[kt][3] = qhu[ib*16 + 8*kt + tid + 4];
        }
        const float2* b0f = (const float2*)(bfp + (size_t)ia*JJ);
        const float2* b1f = (const float2*)(bfp + (size_t)ib*JJ);

        float s0a = 0.f, s0b = 0.f, s1a = 0.f, s1b = 0.f;
        float D0[4], D1[4], D2[4], D3[4];
        #pragma unroll
        for (int k = 0; k < 4; k++) { D0[k]=0.f; D1[k]=0.f; D2[k]=0.f; D3[k]=0.f; }

        #pragma unroll 1
        for (int ch = 0; ch < 4; ch++) {
            int u0 = ch*32;            // float2 unit offset (64 j)
            float S0[16], S1[16];
            // bias (exp2-domain, shift folded) as initial accumulator
            #pragma unroll
            for (int nt = 0; nt < 8; nt++) {
                float2 bf = b0f[u0 + nt*4 + tid];
                S0[2*nt] = bf.x; S0[2*nt+1] = bf.y;
                bf = b1f[u0 + nt*4 + tid];
                S1[2*nt] = bf.x; S1[2*nt+1] = bf.y;
            }
            // QK^T
            #pragma unroll
            for (int nt = 0; nt < 8; nt++) {
                int j = ch*64 + nt*8 + g;
                const uint32_t* kr = Ksb + j*16;
                int rot = 2*j;
                uint32_t b00 = kr[(tid      + rot) & 15];
                uint32_t b01 = kr[(tid + 4  + rot) & 15];
                uint32_t b10 = kr[(tid + 8  + rot) & 15];
                uint32_t b11 = kr[(tid + 12 + rot) & 15];
                mma_f16(S0[2*nt], S0[2*nt+1], S1[2*nt], S1[2*nt+1],
                        A[0][0], A[0][1], A[0][2], A[0][3], b00, b01);
                mma_f16(S0[2*nt], S0[2*nt+1], S1[2*nt], S1[2*nt+1],
                        A[1][0], A[1][1], A[1][2], A[1][3], b10, b11);
            }
            // single-op exp2; pack for AV
            uint32_t h0[8], h1[8];
            #pragma unroll
            for (int nt = 0; nt < 8; nt++) {
                float e0 = ex2(S0[2*nt]);
                float e1 = ex2(S0[2*nt+1]);
                float e2 = ex2(S1[2*nt]);
                float e3 = ex2(S1[2*nt+1]);
                if (nt & 1) { s0b += e0 + e1; s1b += e2 + e3; }
                else        { s0a += e0 + e1; s1a += e2 + e3; }
                h0[nt] = packh2(e0, e1);
                h1[nt] = packh2(e2, e3);
            }
            #pragma unroll
            for (int kt = 0; kt < 4; kt++) {
                uint32_t a0 = h0[2*kt], a1 = h1[2*kt];
                uint32_t a2 = h0[2*kt+1], a3 = h1[2*kt+1];
                int ktg = ch*4 + kt;
                #pragma unroll
                for (int nv = 0; nv < 4; nv++) {
                    int c = nv*8 + g;
                    const uint32_t* vr = Vtb + c*128;
                    int rot = 4*c + 8*ktg + tid;
                    uint32_t b0 = vr[ rot      & 127];
                    uint32_t b1 = vr[(rot + 4) & 127];
                    float* D = (nv==0) ? D0 : (nv==1) ? D1 : (nv==2) ? D2 : D3;
                    mma_f16(D[0], D[1], D[2], D[3], a0, a1, a2, a3, b0, b1);
                }
            }
        }

        float s0 = s0a + s0b, s1 = s1a + s1b;
        s0 += __shfl_xor_sync(0xffffffffu, s0, 1);
        s0 += __shfl_xor_sync(0xffffffffu, s0, 2);
        s1 += __shfl_xor_sync(0xffffffffu, s1, 1);
        s1 += __shfl_xor_sync(0xffffffffu, s1, 2);
        float inv0 = 1.f / s0, inv1 = 1.f / s1;

        // epilogue: gate + store half2
        uint32_t* ou = (uint32_t*)g_oh;
        #pragma unroll
        for (int nv = 0; nv < 4; nv++) {
            const float* D = (nv==0) ? D0 : (nv==1) ? D1 : (nv==2) ? D2 : D3;
            float2 ga = h2f2(ghu[ia*16 + nv*4 + tid]);
            float2 gb = h2f2(ghu[ib*16 + nv*4 + tid]);
            int cu = (h*CC)/2 + nv*4 + tid;
            ou[(size_t)(s*II + ia)*(HH*CC/2) + cu] = packh2(D[0]*inv0*ga.x, D[1]*inv0*ga.y);
            ou[(size_t)(s*II + ib)*(HH*CC/2) + cu] = packh2(D[2]*inv1*gb.x, D[3]*inv1*gb.y);
        }
    }
}

// ---------------------------------------------------------------------------
// Kernel D: out = o @ wo + bo via fp16 m16n8k16. M-tile=64, 128 threads.
//   o tile batched into registers FIRST; wT staging work hides the latency.
// ---------------------------------------------------------------------------
#define OUT_SMEM_BYTES ((64*132 + 32*128 + 32) * 4)
__global__ __launch_bounds__(128, 4) void outproj_kernel(
    const float* __restrict__ wo, const float* __restrict__ bo,
    float* __restrict__ out)
{
    extern __shared__ uint32_t smu[];
    uint32_t* oS = smu;                 // [64][132]
    uint32_t* wT = oS + 64*132;         // [32][128]
    float*   sbo = (float*)(wT + 32*128);

    int t = threadIdx.x, lane = t & 31, w = t >> 5;
    int g = lane >> 2, tid = lane & 3;
    int r0 = blockIdx.x * 64;

    // 1) issue all o loads (16 uint4 per thread, coalesced)
    uint4 ov[16];
    const uint4* op = (const uint4*)((const uint32_t*)g_oh + (size_t)r0*(HH*CC/2));
    #pragma unroll
    for (int i = 0; i < 16; i++) ov[i] = op[t + 128*i];

    // 2) independent work: stage wo transposed + cvt
    for (int idx = t; idx < 4096; idx += 128) {
        int u = idx >> 5, c = idx & 31;
        float w0 = wo[(2*u)*32 + c];
        float w1 = wo[(2*u+1)*32 + c];
        wT[c*128 + ((u + 4*c) & 127)] = packh2(w0, w1);
    }
    if (t < 32) sbo[t] = bo[t];

    // 3) store o tiles to smem
    #pragma unroll
    for (int i = 0; i < 16; i++) {
        int idx = t + 128*i;
        int r = idx >> 5, u4 = idx & 31;
        *(uint4*)&oS[r*132 + 4*u4] = ov[i];
    }
    __syncthreads();

    int iw = w*16;
    float D0[4], D1[4], D2[4], D3[4];
    #pragma unroll
    for (int k = 0; k < 4; k++) { D0[k]=0.f; D1[k]=0.f; D2[k]=0.f; D3[k]=0.f; }

    #pragma unroll 4
    for (int kt = 0; kt < 16; kt++) {
        int u = 8*kt + tid;
        uint32_t a0 = oS[(iw+g  )*132 + u];
        uint32_t a1 = oS[(iw+g+8)*132 + u];
        uint32_t a2 = oS[(iw+g  )*132 + u + 4];
        uint32_t a3 = oS[(iw+g+8)*132 + u + 4];
        #pragma unroll
        for (int nt = 0; nt < 4; nt++) {
            int c = nt*8 + g;
            const uint32_t* wr = wT + c*128;
            int rot = 4*c + 8*kt + tid;
            uint32_t b0 = wr[ rot      & 127];
            uint32_t b1 = wr[(rot + 4) & 127];
            float* D = (nt == 0) ? D0 : (nt == 1) ? D1 : (nt == 2) ? D2 : D3;
            mma_f16(D[0], D[1], D[2], D[3], a0, a1, a2, a3, b0, b1);
        }
    }

    int ra = r0 + iw + g, rb = r0 + iw + g + 8;
    #pragma unroll
    for (int nt = 0; nt < 4; nt++) {
        const float* D = (nt == 0) ? D0 : (nt == 1) ? D1 : (nt == 2) ? D2 : D3;
        int c = nt*8 + 2*tid;
        float2 bb = make_float2(sbo[c], sbo[c+1]);
        *(float2*)&out[(size_t)ra*CC + c] = make_float2(D[0] + bb.x, D[1] + bb.y);
        *(float2*)&out[(size_t)rb*CC + c] = make_float2(D[2] + bb.x, D[3] + bb.y);
    }
}

// ---------------------------------------------------------------------------
extern "C" void kernel_launch(void* const* d_in, const int* in_sizes, int n_in,
                              void* d_out, int out_size)
{
    const float* m         = (const float*)d_in[0];
    const float* z         = (const float*)d_in[1];
    const float* ln_scale  = (const float*)d_in[2];
    const float* ln_bias   = (const float*)d_in[3];
    const float* lnb_scale = (const float*)d_in[4];
    const float* lnb_bias  = (const float*)d_in[5];
    const float* wq        = (const float*)d_in[6];
    const float* wk        = (const float*)d_in[7];
    const float* wv        = (const float*)d_in[8];
    const float* wb        = (const float*)d_in[9];
    const float* wg        = (const float*)d_in[10];
    const float* wo        = (const float*)d_in[11];
    const float* bo        = (const float*)d_in[12];
    float* out = (float*)d_out;

    cudaFuncSetAttribute(proj_kernel, cudaFuncAttributeMaxDynamicSharedMemorySize,
                         PROJ_SM_WORDS * 4);
    cudaFuncSetAttribute(outproj_kernel, cudaFuncAttributeMaxDynamicSharedMemorySize,
                         OUT_SMEM_BYTES);

    wprep_kernel<<<64, 256>>>(wq, wk, wv, wg);
    // Fused proj (blocks 0..511) + bias (blocks 512..767)
    proj_kernel<<<768, 256, PROJ_SM_WORDS*4>>>(m, ln_scale, ln_bias,
                                               z, lnb_scale, lnb_bias, wb);
    attn_kernel<<<SS*HH, 256>>>();
    outproj_kernel<<<NROW/64, 128, OUT_SMEM_BYTES>>>(wo, bo, out);
}